// round 13
// baseline (speedup 1.0000x reference)
#include <cuda_runtime.h>
#include <cuda_bf16.h>
#include <cuda_fp16.h>
#include <math.h>
#include <stdint.h>

#define HD   1024
#define K2   2048
#define BB   8
#define SS   4096
#define LL   64
#define M512 (BB*LL)

// ---- device scratch ----
__device__ __nv_bfloat16 g_Wt_h[K2 * HD];
__device__ __nv_bfloat16 g_Wt_l[K2 * HD];
__device__ __half        g_W16[HD * K2];
__device__ __half        g_Wh_h[M512 * K2];
__device__ __half        g_Wh_l[M512 * K2];
__device__ float         g_bh[M512];
__device__ float         g_scores[(size_t)M512 * SS];
__device__ float         g_m[M512];
__device__ float         g_inv[M512];
__device__ __half        g_w_h[(size_t)M512 * SS];
__device__ __half        g_w_l[(size_t)M512 * SS];
__device__ float         g_ctx2f[M512 * K2];

// ---- helpers ----
__device__ __forceinline__ uint32_t smem_u32(const void* p) {
    uint32_t a;
    asm("{ .reg .u64 t; cvta.to.shared.u64 t, %1; cvt.u32.u64 %0, t; }" : "=r"(a) : "l"(p));
    return a;
}
__device__ __forceinline__ void split2(float x0, float x1, uint32_t& h, uint32_t& l) {
    __nv_bfloat162 hh = __floats2bfloat162_rn(x0, x1);
    h = *(uint32_t*)&hh;
    float h0 = __uint_as_float(h << 16);
    float h1 = __uint_as_float(h & 0xFFFF0000u);
    __nv_bfloat162 ll = __floats2bfloat162_rn(x0 - h0, x1 - h1);
    l = *(uint32_t*)&ll;
}
__device__ __forceinline__ void split2h(float x0, float x1, uint32_t& h, uint32_t& l) {
    __half2 hh = __floats2half2_rn(x0, x1);
    h = *(uint32_t*)&hh;
    float2 hf = __half22float2(hh);
    __half2 ll = __floats2half2_rn(x0 - hf.x, x1 - hf.y);
    l = *(uint32_t*)&ll;
}
__device__ __forceinline__ uint32_t packh(float x0, float x1) {
    __half2 hh = __floats2half2_rn(x0, x1);
    return *(uint32_t*)&hh;
}
__device__ __forceinline__ void mma_bf16(float* d, const uint32_t* a, uint32_t b0, uint32_t b1) {
    asm volatile(
        "mma.sync.aligned.m16n8k16.row.col.f32.bf16.bf16.f32 "
        "{%0,%1,%2,%3}, {%4,%5,%6,%7}, {%8,%9}, {%0,%1,%2,%3};"
        : "+f"(d[0]), "+f"(d[1]), "+f"(d[2]), "+f"(d[3])
        : "r"(a[0]), "r"(a[1]), "r"(a[2]), "r"(a[3]), "r"(b0), "r"(b1));
}
__device__ __forceinline__ void mma_fp16(float* d, const uint32_t* a, uint32_t b0, uint32_t b1) {
    asm volatile(
        "mma.sync.aligned.m16n8k16.row.col.f32.f16.f16.f32 "
        "{%0,%1,%2,%3}, {%4,%5,%6,%7}, {%8,%9}, {%0,%1,%2,%3};"
        : "+f"(d[0]), "+f"(d[1]), "+f"(d[2]), "+f"(d[3])
        : "r"(a[0]), "r"(a[1]), "r"(a[2]), "r"(a[3]), "r"(b0), "r"(b1));
}
__device__ __forceinline__ void ldmx4(uint32_t* r, uint32_t addr) {
    asm volatile("ldmatrix.sync.aligned.m8n8.x4.shared.b16 {%0,%1,%2,%3}, [%4];"
                 : "=r"(r[0]), "=r"(r[1]), "=r"(r[2]), "=r"(r[3]) : "r"(addr));
}
__device__ __forceinline__ void ldmx4t(uint32_t* r, uint32_t addr) {
    asm volatile("ldmatrix.sync.aligned.m8n8.x4.trans.shared.b16 {%0,%1,%2,%3}, [%4];"
                 : "=r"(r[0]), "=r"(r[1]), "=r"(r[2]), "=r"(r[3]) : "r"(addr));
}
__device__ __forceinline__ void cpa16(uint32_t s, const void* g) {
    asm volatile("cp.async.cg.shared.global [%0], [%1], 16;" :: "r"(s), "l"(g));
}
__device__ __forceinline__ void cpa_commit() {
    asm volatile("cp.async.commit_group;" ::: "memory");
}
template <int N>
__device__ __forceinline__ void cpa_wait() {
    asm volatile("cp.async.wait_group %0;" :: "n"(N) : "memory");
}
__device__ __forceinline__ uint32_t ofs64(int r, int k) {
    return (uint32_t)(r * 64 + k * 2) ^ (uint32_t)(((r >> 1) & 3) << 4);
}
__device__ __forceinline__ uint32_t ofs128(int r, int k) {
    return (uint32_t)(r * 128 + k * 2) ^ (uint32_t)((r & 7) << 4);
}
__device__ __forceinline__ uint32_t ofs256(int r, int k) {
    return (uint32_t)(r * 256 + k * 2) ^ (uint32_t)((r & 7) << 4);
}
__device__ __forceinline__ uint32_t bofs(int l, int ko) {
    return ((uint32_t)(ko >> 6) << 13) +
           ((((uint32_t)l << 7) + (uint32_t)((ko & 63) << 1)) ^ (uint32_t)((l & 7) << 4));
}

// ---------------------------------------------------------------------------
__global__ __launch_bounds__(256) void k0_wt(const float* __restrict__ W) {
    __shared__ float tile[32][33];
    int n0 = blockIdx.x * 32, h0 = blockIdx.y * 32;
    int tx = threadIdx.x & 31, ty = threadIdx.x >> 5;
    #pragma unroll
    for (int r = 0; r < 4; r++) {
        int h = h0 + ty + r * 8;
        float v = W[(size_t)h * K2 + n0 + tx];
        tile[ty + r * 8][tx] = v;
        g_W16[(size_t)h * K2 + n0 + tx] = __float2half_rn(v);
    }
    __syncthreads();
    #pragma unroll
    for (int r = 0; r < 4; r++) {
        int n = n0 + ty + r * 8;
        float x = tile[tx][ty + r * 8];
        __nv_bfloat16 h = __float2bfloat16_rn(x);
        g_Wt_h[(size_t)n * HD + h0 + tx] = h;
        g_Wt_l[(size_t)n * HD + h0 + tx] = __float2bfloat16_rn(x - __bfloat162float(h));
    }
}

__global__ __launch_bounds__(256) void k_zero() {
    size_t i = ((size_t)blockIdx.x * 256 + threadIdx.x) * 4;
    *(float4*)(g_ctx2f + i) = make_float4(0.f, 0.f, 0.f, 0.f);
}

__global__ __launch_bounds__(256) void k_bh(const float* __restrict__ hidden,
                                            const float* __restrict__ bias) {
    int w = (blockIdx.x * 256 + threadIdx.x) >> 5;
    int lane = threadIdx.x & 31;
    int b = w >> 6, l = w & 63;
    const float* hrow = hidden + (l * BB + b) * HD;
    float s = 0.f;
    for (int h = lane; h < HD; h += 32) s += bias[h] * hrow[h];
    #pragma unroll
    for (int o = 16; o; o >>= 1) s += __shfl_xor_sync(0xffffffffu, s, o);
    if (lane == 0) g_bh[w] = s;
}

// ---------------------------------------------------------------------------
// K1 (mma, bf16 3-term): Wh[m,n] = hidden_row(m) . Wt[n]; emit fp16 hi/lo.
// ---------------------------------------------------------------------------
__global__ __launch_bounds__(256) void k1_mma(const float* __restrict__ hidden) {
    __shared__ __align__(128) uint8_t sm[32768];
    const int tid = threadIdx.x, w = tid >> 5, lane = tid & 31;
    const int grp = lane >> 2, tig = lane & 3;
    const int m0 = blockIdx.y * 128 + w * 16;
    const int n0 = blockIdx.x * 64;
    uint32_t sbase = smem_u32(sm);
    int mA = m0 + grp, mB = mA + 8;
    const float* row0 = hidden + (size_t)((mA & 63) * BB + (mA >> 6)) * HD;
    const float* row1 = hidden + (size_t)((mB & 63) * BB + (mB >> 6)) * HD;

    const int srow = tid >> 2, skp = (tid & 3) * 16;
    const __nv_bfloat16* sh = g_Wt_h + (size_t)(n0 + srow) * HD + skp;
    const __nv_bfloat16* sl = g_Wt_l + (size_t)(n0 + srow) * HD + skp;
    const uint32_t so1 = bofs(srow, skp), so2 = bofs(srow, skp + 8);

    cpa16(sbase + so1, sh);           cpa16(sbase + so2, sh + 8);
    cpa16(sbase + so1 + 8192, sl);    cpa16(sbase + so2 + 8192, sl + 8);
    cpa_commit();

    float d[8][4];
    #pragma unroll
    for (int i = 0; i < 8; i++) { d[i][0]=d[i][1]=d[i][2]=d[i][3]=0.f; }

    float2 nv0 = *(const float2*)(row0 + tig * 2);
    float2 nv1 = *(const float2*)(row1 + tig * 2);
    float2 nv2 = *(const float2*)(row0 + tig * 2 + 8);
    float2 nv3 = *(const float2*)(row1 + tig * 2 + 8);

    for (int c = 0; c < 16; c++) {
        uint32_t bb = (uint32_t)(c & 1) * 16384;
        if (c < 15) {
            uint32_t db = sbase + (uint32_t)((c + 1) & 1) * 16384;
            const __nv_bfloat16* nh = sh + (c + 1) * 64;
            const __nv_bfloat16* nl = sl + (c + 1) * 64;
            cpa16(db + so1, nh);         cpa16(db + so2, nh + 8);
            cpa16(db + so1 + 8192, nl);  cpa16(db + so2 + 8192, nl + 8);
            cpa_commit();
            cpa_wait<1>();
        } else {
            cpa_wait<0>();
        }
        __syncthreads();
        #pragma unroll
        for (int ks = 0; ks < 4; ks++) {
            float2 v0 = nv0, v1 = nv1, v2 = nv2, v3 = nv3;
            int g = c * 4 + ks;
            if (g < 63) {
                const float* a0 = row0 + (g + 1) * 16 + tig * 2;
                const float* a1 = row1 + (g + 1) * 16 + tig * 2;
                nv0 = *(const float2*)a0;       nv1 = *(const float2*)a1;
                nv2 = *(const float2*)(a0 + 8); nv3 = *(const float2*)(a1 + 8);
            }
            uint32_t ah[4], al[4];
            split2(v0.x, v0.y, ah[0], al[0]);
            split2(v1.x, v1.y, ah[1], al[1]);
            split2(v2.x, v2.y, ah[2], al[2]);
            split2(v3.x, v3.y, ah[3], al[3]);
            int kol = ks * 16 + (lane & 8);
            uint32_t bh4[4][4], bl4[4][4];
            #pragma unroll
            for (int np = 0; np < 4; np++) {
                int lr = np * 16 + (lane & 7) + ((lane >> 1) & 8);
                uint32_t addr = sbase + bb + bofs(lr, kol);
                ldmx4(bh4[np], addr);
                ldmx4(bl4[np], addr + 8192);
            }
            #pragma unroll
            for (int np = 0; np < 4; np++) {
                mma_bf16(d[2*np],   ah, bh4[np][0], bh4[np][1]);
                mma_bf16(d[2*np+1], ah, bh4[np][2], bh4[np][3]);
            }
            #pragma unroll
            for (int np = 0; np < 4; np++) {
                mma_bf16(d[2*np],   al, bh4[np][0], bh4[np][1]);
                mma_bf16(d[2*np+1], al, bh4[np][2], bh4[np][3]);
            }
            #pragma unroll
            for (int np = 0; np < 4; np++) {
                mma_bf16(d[2*np],   ah, bl4[np][0], bl4[np][1]);
                mma_bf16(d[2*np+1], ah, bl4[np][2], bl4[np][3]);
            }
        }
        __syncthreads();
    }
    #pragma unroll
    for (int nt = 0; nt < 8; nt++) {
        int np = n0 + nt * 8 + tig * 2;
        uint32_t h01, l01, h23, l23;
        split2h(d[nt][0], d[nt][1], h01, l01);
        split2h(d[nt][2], d[nt][3], h23, l23);
        *(uint32_t*)(g_Wh_h + (size_t)mA * K2 + np) = h01;
        *(uint32_t*)(g_Wh_l + (size_t)mA * K2 + np) = l01;
        *(uint32_t*)(g_Wh_h + (size_t)mB * K2 + np) = h23;
        *(uint32_t*)(g_Wh_l + (size_t)mB * K2 + np) = l23;
    }
}

// ---------------------------------------------------------------------------
// K2 v4 (mma, fp16 3-term) — R12 verbatim (at HMMA floor).
// ---------------------------------------------------------------------------
__global__ __launch_bounds__(256, 2) void k2_mma(const float* __restrict__ enc) {
    extern __shared__ __align__(128) uint8_t sm[];
    const int tid = threadIdx.x, w = tid >> 5, lane = tid & 31;
    const int grp = lane >> 2, tig = lane & 3;
    const int b = blockIdx.y, sBlk = blockIdx.x * 128;
    const int kg = w >> 2, ws = w & 3, sW = ws * 32;
    uint32_t sb = smem_u32(sm);
    const float* encb = enc + (size_t)b * SS * K2;
    const __half* Bhp = g_Wh_h + (size_t)b * 64 * K2;
    const __half* Blp = g_Wh_l + (size_t)b * 64 * K2;

    const int tg = tid >> 7, si = tid & 127;
    const int brow = si >> 1, part = si & 1;
    const uint32_t bd0 = ofs64(brow, part * 16), bd1 = ofs64(brow, part * 16 + 8);

    auto stage = [&](int c, int p) {
        uint32_t base = sb + (uint32_t)(tg * 2 + p) * 8192;
        size_t go = (size_t)brow * K2 + tg * 1024 + c * 32 + part * 16;
        cpa16(base + bd0, Bhp + go);
        cpa16(base + bd1, Bhp + go + 8);
        cpa16(base + 4096 + bd0, Blp + go);
        cpa16(base + 4096 + bd1, Blp + go + 8);
    };

    stage(0, 0);
    cpa_commit();

    float d[2][8][4];
    #pragma unroll
    for (int i = 0; i < 2; i++)
        #pragma unroll
        for (int j = 0; j < 8; j++) { d[i][j][0]=d[i][j][1]=d[i][j][2]=d[i][j][3]=0.f; }

    const float* arow0 = encb + (size_t)(sBlk + sW + grp) * K2 + kg * 1024 + tig * 2;

    for (int c = 0; c < 32; c++) {
        int p = c & 1;
        cpa_wait<0>();
        __syncthreads();
        if (c < 31) { stage(c + 1, p ^ 1); cpa_commit(); }
        uint32_t bbase = sb + (uint32_t)(kg * 2 + p) * 8192;
        #pragma unroll
        for (int ks = 0; ks < 2; ks++) {
            const float* a0 = arow0 + c * 32 + ks * 16;
            float2 u0 = *(const float2*)(a0);
            float2 u1 = *(const float2*)(a0 + 8 * K2);
            float2 u2 = *(const float2*)(a0 + 8);
            float2 u3 = *(const float2*)(a0 + 8 * K2 + 8);
            float2 w0 = *(const float2*)(a0 + 16 * K2);
            float2 w1 = *(const float2*)(a0 + 24 * K2);
            float2 w2 = *(const float2*)(a0 + 16 * K2 + 8);
            float2 w3 = *(const float2*)(a0 + 24 * K2 + 8);
            uint32_t ahA[4], alA[4], ahB[4], alB[4];
            split2h(u0.x, u0.y, ahA[0], alA[0]);
            split2h(u1.x, u1.y, ahA[1], alA[1]);
            split2h(u2.x, u2.y, ahA[2], alA[2]);
            split2h(u3.x, u3.y, ahA[3], alA[3]);
            split2h(w0.x, w0.y, ahB[0], alB[0]);
            split2h(w1.x, w1.y, ahB[1], alB[1]);
            split2h(w2.x, w2.y, ahB[2], alB[2]);
            split2h(w3.x, w3.y, ahB[3], alB[3]);
            int bcol = ks * 16 + (lane & 8);
            int br = (lane & 7) + ((lane >> 1) & 8);
            #pragma unroll
            for (int hf = 0; hf < 2; hf++) {
                uint32_t bh4[2][4], bl4[2][4];
                #pragma unroll
                for (int q = 0; q < 2; q++) {
                    int nb = hf * 2 + q;
                    uint32_t addr = bbase + ofs64(nb * 16 + br, bcol);
                    ldmx4(bh4[q], addr);
                    ldmx4(bl4[q], addr + 4096);
                }
                #pragma unroll
                for (int q = 0; q < 2; q++) {
                    mma_fp16(d[0][hf*4 + q*2],     ahA, bh4[q][0], bh4[q][1]);
                    mma_fp16(d[0][hf*4 + q*2 + 1], ahA, bh4[q][2], bh4[q][3]);
                    mma_fp16(d[1][hf*4 + q*2],     ahB, bh4[q][0], bh4[q][1]);
                    mma_fp16(d[1][hf*4 + q*2 + 1], ahB, bh4[q][2], bh4[q][3]);
                }
                #pragma unroll
                for (int q = 0; q < 2; q++) {
                    mma_fp16(d[0][hf*4 + q*2],     alA, bh4[q][0], bh4[q][1]);
                    mma_fp16(d[0][hf*4 + q*2 + 1], alA, bh4[q][2], bh4[q][3]);
                    mma_fp16(d[1][hf*4 + q*2],     alB, bh4[q][0], bh4[q][1]);
                    mma_fp16(d[1][hf*4 + q*2 + 1], alB, bh4[q][2], bh4[q][3]);
                }
                #pragma unroll
                for (int q = 0; q < 2; q++) {
                    mma_fp16(d[0][hf*4 + q*2],     ahA, bl4[q][0], bl4[q][1]);
                    mma_fp16(d[0][hf*4 + q*2 + 1], ahA, bl4[q][2], bl4[q][3]);
                    mma_fp16(d[1][hf*4 + q*2],     ahB, bl4[q][0], bl4[q][1]);
                    mma_fp16(d[1][hf*4 + q*2 + 1], ahB, bl4[q][2], bl4[q][3]);
                }
            }
        }
    }

    __syncthreads();
    float* acc = (float*)sm;
    if (kg == 1) {
        #pragma unroll
        for (int mb = 0; mb < 2; mb++)
            #pragma unroll
            for (int nb = 0; nb < 8; nb++) {
                int sl = sW + mb * 16 + grp;
                int cl = nb * 8 + tig * 2;
                *(float2*)&acc[sl * 68 + cl]       = make_float2(d[mb][nb][0], d[mb][nb][1]);
                *(float2*)&acc[(sl + 8) * 68 + cl] = make_float2(d[mb][nb][2], d[mb][nb][3]);
            }
    }
    __syncthreads();
    if (kg == 0) {
        #pragma unroll
        for (int mb = 0; mb < 2; mb++)
            #pragma unroll
            for (int nb = 0; nb < 8; nb++) {
                int sl = sW + mb * 16 + grp;
                int cl = nb * 8 + tig * 2;
                float b0v = g_bh[b * 64 + cl], b1v = g_bh[b * 64 + cl + 1];
                float2 o0 = *(const float2*)&acc[sl * 68 + cl];
                float2 o1 = *(const float2*)&acc[(sl + 8) * 68 + cl];
                size_t q0 = (size_t)(b * 64 + cl) * SS + sBlk, q1 = q0 + SS;
                g_scores[q0 + sl]     = d[mb][nb][0] + o0.x + b0v;
                g_scores[q1 + sl]     = d[mb][nb][1] + o0.y + b1v;
                g_scores[q0 + sl + 8] = d[mb][nb][2] + o1.x + b0v;
                g_scores[q1 + sl + 8] = d[mb][nb][3] + o1.y + b1v;
            }
    }
}

// ---------------------------------------------------------------------------
__global__ __launch_bounds__(256) void k3a() {
    int row = blockIdx.x, t = threadIdx.x;
    const float4* p = (const float4*)(g_scores + (size_t)row * SS) + t;
    float4 v[4];
    #pragma unroll
    for (int i = 0; i < 4; i++) v[i] = p[i * 256];
    float m = -1e30f;
    #pragma unroll
    for (int i = 0; i < 4; i++)
        m = fmaxf(m, fmaxf(fmaxf(v[i].x, v[i].y), fmaxf(v[i].z, v[i].w)));
    __shared__ float red[256];
    red[t] = m; __syncthreads();
    #pragma unroll
    for (int o = 128; o; o >>= 1) { if (t < o) red[t] = fmaxf(red[t], red[t + o]); __syncthreads(); }
    m = red[0]; __syncthreads();
    float s = 0.f;
    #pragma unroll
    for (int i = 0; i < 4; i++)
        s += expf(v[i].x - m) + expf(v[i].y - m) + expf(v[i].z - m) + expf(v[i].w - m);
    red[t] = s; __syncthreads();
    #pragma unroll
    for (int o = 128; o; o >>= 1) { if (t < o) red[t] += red[t + o]; __syncthreads(); }
    if (t == 0) { g_m[row] = m; g_inv[row] = 1.f / red[0]; }
}

__global__ __launch_bounds__(256) void k3b(float* __restrict__ out_w) {
    int b = blockIdx.y, s0 = blockIdx.x * 128;
    int t = threadIdx.x, l = t >> 2, q = t & 3;
    int row = b * 64 + l;
    float m = g_m[row], inv = g_inv[row];
    int sb0 = s0 + q * 32;
    const float* p = g_scores + (size_t)row * SS + sb0;
    uint32_t hb[16], lb[16];
    #pragma unroll
    for (int j = 0; j < 16; j++) {
        float2 x = *(const float2*)(p + j * 2);
        float w0 = expf(x.x - m) * inv;
        float w1 = expf(x.y - m) * inv;
        out_w[((size_t)b * SS + sb0 + j * 2) * LL + l]     = w0;
        out_w[((size_t)b * SS + sb0 + j * 2 + 1) * LL + l] = w1;
        split2h(w0, w1, hb[j], lb[j]);
    }
    size_t wo = (size_t)row * SS + sb0;
    #pragma unroll
    for (int j = 0; j < 4; j++) {
        *(uint4*)(g_w_h + wo + j * 8) = make_uint4(hb[4*j], hb[4*j+1], hb[4*j+2], hb[4*j+3]);
        *(uint4*)(g_w_l + wo + j * 8) = make_uint4(lb[4*j], lb[4*j+1], lb[4*j+2], lb[4*j+3]);
    }
}

// ---------------------------------------------------------------------------
// K4 v2 (mma, fp16 1-term): ctx2[l,k] = sum_s w_hi[l,s] enc_hi[s,k]
// 256 thr, __launch_bounds__(256,2). grid (32,8): kt = bx&15 (k-tile 128),
// sh = bx>>4 (s-half 2048). 8 warps = 4 wk x 2 sg; warp tile 32k x 64l.
// smem: A [64s][128k] fp16 (ofs256) @ p*16384; B w-hi [64l][64s] (ofs128)
//       @ 32768 + p*8192; acc fp32 [128k][67] overlaid @ 0. Total 49152.
// Cross-CTA s-reduction via atomicAdd into g_ctx2f (2 adds, deterministic).
// ---------------------------------------------------------------------------
__global__ __launch_bounds__(256, 2) void k4_mma(const float* __restrict__ enc) {
    extern __shared__ __align__(128) uint8_t sm[];
    const int tid = threadIdx.x, w = tid >> 5, lane = tid & 31;
    const int grp = lane >> 2, tig = lane & 3;
    const int wk = w & 3, sg = w >> 2;
    const int b = blockIdx.y;
    const int kb0 = (blockIdx.x & 15) * 128;
    const int sh0 = (blockIdx.x >> 4) * 2048;
    const int m0w = wk * 32;
    uint32_t sb = smem_u32(sm);
    const float* encb = enc + (size_t)b * SS * K2;
    const __half* Bh = g_w_h + (size_t)b * 64 * SS;

    const int as = tid >> 2, akp = (tid & 3) * 32;
    const int brow = tid >> 2, bso = (tid & 3) * 16;

    uint32_t ph[16];
    uint4 pb0, pb1;
    auto ldg = [&](int c) {
        int s0 = sh0 + c * 64;
        const float* ap = encb + (size_t)(s0 + as) * K2 + kb0 + akp;
        #pragma unroll
        for (int j = 0; j < 8; j++) {
            float4 v = *(const float4*)(ap + j * 4);
            ph[j*2]   = packh(v.x, v.y);
            ph[j*2+1] = packh(v.z, v.w);
        }
        const __half* bp = Bh + (size_t)brow * SS + s0 + bso;
        pb0 = *(const uint4*)(bp);
        pb1 = *(const uint4*)(bp + 8);
    };
    auto sts = [&](int p) {
        uint32_t ab = (uint32_t)p * 16384;
        *(uint4*)(sm + ab + ofs256(as, akp))      = make_uint4(ph[0], ph[1], ph[2], ph[3]);
        *(uint4*)(sm + ab + ofs256(as, akp + 8))  = make_uint4(ph[4], ph[5], ph[6], ph[7]);
        *(uint4*)(sm + ab + ofs256(as, akp + 16)) = make_uint4(ph[8], ph[9], ph[10], ph[11]);
        *(uint4*)(sm + ab + ofs256(as, akp + 24)) = make_uint4(ph[12], ph[13], ph[14], ph[15]);
        uint32_t bb = 32768u + (uint32_t)p * 8192;
        *(uint4*)(sm + bb + ofs128(brow, bso))     = pb0;
        *(uint4*)(sm + bb + ofs128(brow, bso + 8)) = pb1;
    };

    float d[2][8][4];
    #pragma unroll
    for (int i = 0; i < 2; i++)
        #pragma unroll
        for (int j = 0; j < 8; j++) { d[i][j][0]=d[i][j][1]=d[i][j][2]=d[i][j][3]=0.f; }

    ldg(0);
    for (int c = 0; c < 32; c++) {
        int p = c & 1;
        sts(p);
        __syncthreads();
        if (c < 31) ldg(c + 1);
        uint32_t ab = sb + (uint32_t)p * 16384;
        uint32_t bb = sb + 32768u + (uint32_t)p * 8192;
        #pragma unroll
        for (int j = 0; j < 2; j++) {
            int ks = sg * 2 + j;
            int srow = ks * 16 + (lane & 7) + ((lane >> 4) & 1) * 8;
            int mcb  = ((lane >> 3) & 1) * 8;
            uint32_t a0[4], a1[4];
            ldmx4t(a0, ab + ofs256(srow, m0w + mcb));
            ldmx4t(a1, ab + ofs256(srow, m0w + 16 + mcb));
            int bcol = ks * 16 + (lane & 8);
            int br = (lane & 7) + ((lane >> 1) & 8);
            uint32_t bh4[4][4];
            #pragma unroll
            for (int np = 0; np < 4; np++)
                ldmx4(bh4[np], bb + ofs128(np * 16 + br, bcol));
            #pragma unroll
            for (int np = 0; np < 4; np++) {
                mma_fp16(d[0][2*np],   a0, bh4[np][0], bh4[np][1]);
                mma_fp16(d[0][2*np+1], a0, bh4[np][2], bh4[np][3]);
                mma_fp16(d[1][2*np],   a1, bh4[np][0], bh4[np][1]);
                mma_fp16(d[1][2*np+1], a1, bh4[np][2], bh4[np][3]);
            }
        }
        __syncthreads();
    }

    // sg-split-2 reduction in smem acc[k][l], then atomicAdd to g_ctx2f
    float* acc = (float*)sm;
    if (sg == 1) {
        #pragma unroll
        for (int mb = 0; mb < 2; mb++)
            #pragma unroll
            for (int nb = 0; nb < 8; nb++) {
                int k0 = m0w + mb * 16 + grp;
                int c0 = nb * 8 + tig * 2;
                acc[k0 * 67 + c0]           = d[mb][nb][0];
                acc[k0 * 67 + c0 + 1]       = d[mb][nb][1];
                acc[(k0 + 8) * 67 + c0]     = d[mb][nb][2];
                acc[(k0 + 8) * 67 + c0 + 1] = d[mb][nb][3];
            }
    }
    __syncthreads();
    if (sg == 0) {
        #pragma unroll
        for (int mb = 0; mb < 2; mb++)
            #pragma unroll
            for (int nb = 0; nb < 8; nb++) {
                int k0 = m0w + mb * 16 + grp;
                int c0 = nb * 8 + tig * 2;
                acc[k0 * 67 + c0]           += d[mb][nb][0];
                acc[k0 * 67 + c0 + 1]       += d[mb][nb][1];
                acc[(k0 + 8) * 67 + c0]     += d[mb][nb][2];
                acc[(k0 + 8) * 67 + c0 + 1] += d[mb][nb][3];
            }
    }
    __syncthreads();
    {
        int l = tid >> 2, kq = (tid & 3) * 32;
        float* dst = g_ctx2f + (size_t)(b * 64 + l) * K2 + kb0 + kq;
        #pragma unroll
        for (int j = 0; j < 32; j++)
            atomicAdd(dst + j, acc[(kq + j) * 67 + l]);
    }
}

// ---------------------------------------------------------------------------
// K5 (mma, fp16 2-term): out[m,h] = bias[h] + sum_k ctx2[m,k] W[h,k]
// A from fp32 g_ctx2f with on-the-fly split2h.
// ---------------------------------------------------------------------------
__global__ __launch_bounds__(256) void k5_mma(const float* __restrict__ bias,
                                              float* __restrict__ out) {
    const int tid = threadIdx.x, w = tid >> 5, lane = tid & 31;
    const int grp = lane >> 2, tig = lane & 3;
    const int m0 = blockIdx.y * 128 + w * 16;
    const int n0 = blockIdx.x * 32;
    int mA = m0 + grp, mB = mA + 8;
    const float* a0p = g_ctx2f + (size_t)mA * K2 + tig * 2;
    const float* a1p = g_ctx2f + (size_t)mB * K2 + tig * 2;

    float d[4][4];
    #pragma unroll
    for (int i = 0; i < 4; i++) { d[i][0]=d[i][1]=d[i][2]=d[i][3]=0.f; }

    #pragma unroll 2
    for (int k0 = 0; k0 < K2; k0 += 16) {
        float2 v0 = *(const float2*)(a0p + k0);
        float2 v1 = *(const float2*)(a1p + k0);
        float2 v2 = *(const float2*)(a0p + k0 + 8);
        float2 v3 = *(const float2*)(a1p + k0 + 8);
        uint32_t ah[4], al[4];
        split2h(v0.x, v0.y, ah[0], al[0]);
        split2h(v1.x, v1.y, ah[1], al[1]);
        split2h(v2.x, v2.y, ah[2], al[2]);
        split2h(v3.x, v3.y, ah[3], al[3]);
        uint32_t bh0[4], bh1[4];
        #pragma unroll
        for (int nt = 0; nt < 4; nt++) {
            const __half* wp = g_W16 + (size_t)(n0 + nt * 8 + grp) * K2 + k0 + 2 * tig;
            bh0[nt] = *(const uint32_t*)(wp);
            bh1[nt] = *(const uint32_t*)(wp + 8);
        }
        #pragma unroll
        for (int nt = 0; nt < 4; nt++) mma_fp16(d[nt], ah, bh0[nt], bh1[nt]);
        #pragma unroll
        for (int nt = 0; nt < 4; nt++) mma_fp16(d[nt], al, bh0[nt], bh1[nt]);
    }
    #pragma unroll
    for (int nt = 0; nt < 4; nt++) {
        int hp = n0 + nt * 8 + tig * 2;
        float2 bv = *(const float2*)(bias + hp);
        float2 o0 = {d[nt][0] + bv.x, d[nt][1] + bv.y};
        float2 o1 = {d[nt][2] + bv.x, d[nt][3] + bv.y};
        *(float2*)(out + (size_t)mA * HD + hp) = o0;
        *(float2*)(out + (size_t)mB * HD + hp) = o1;
    }
}

// ---------------------------------------------------------------------------
extern "C" void kernel_launch(void* const* d_in, const int* in_sizes, int n_in,
                              void* d_out, int out_size) {
    (void)in_sizes; (void)n_in; (void)out_size;
    const float* hidden = (const float*)d_in[0];
    const float* enc    = (const float*)d_in[1];
    const float* W      = (const float*)d_in[2];
    const float* bias   = (const float*)d_in[3];
    float* out_ctx = (float*)d_out;
    float* out_w   = (float*)d_out + (size_t)BB * LL * HD;

    const int SM2 = 34816;
    const int SM4 = 49152;
    cudaFuncSetAttribute(k2_mma, cudaFuncAttributeMaxDynamicSharedMemorySize, SM2);
    cudaFuncSetAttribute(k4_mma, cudaFuncAttributeMaxDynamicSharedMemorySize, SM4);

    k0_wt<<<dim3(64, 32), 256>>>(W);
    k_zero<<<1024, 256>>>();
    k_bh<<<64, 256>>>(hidden, bias);
    k1_mma<<<dim3(32, 4), 256>>>(hidden);
    k2_mma<<<dim3(32, 8), 256, SM2>>>(enc);
    k3a<<<512, 256>>>();
    k3b<<<dim3(32, 8), 256>>>(out_w);
    k4_mma<<<dim3(32, 8), 256, SM4>>>(enc);
    k5_mma<<<dim3(32, 4), 256>>>(bias, out_ctx);
}

// round 14
// speedup vs baseline: 1.0099x; 1.0099x over previous
#include <cuda_runtime.h>
#include <cuda_bf16.h>
#include <cuda_fp16.h>
#include <math.h>
#include <stdint.h>

#define HD   1024
#define K2   2048
#define BB   8
#define SS   4096
#define LL   64
#define M512 (BB*LL)

// ---- device scratch ----
__device__ __nv_bfloat16 g_Wt_h[K2 * HD];
__device__ __nv_bfloat16 g_Wt_l[K2 * HD];
__device__ __half        g_W16[HD * K2];
__device__ __half        g_Wh_h[M512 * K2];
__device__ __half        g_Wh_l[M512 * K2];
__device__ float         g_bh[M512];
__device__ float         g_scores[(size_t)M512 * SS];
__device__ float         g_m[M512];
__device__ float         g_inv[M512];
__device__ __half        g_w_h[(size_t)M512 * SS];
__device__ __half        g_w_l[(size_t)M512 * SS];
__device__ float         g_ctx2f[M512 * K2];

// ---- helpers ----
__device__ __forceinline__ uint32_t smem_u32(const void* p) {
    uint32_t a;
    asm("{ .reg .u64 t; cvta.to.shared.u64 t, %1; cvt.u32.u64 %0, t; }" : "=r"(a) : "l"(p));
    return a;
}
__device__ __forceinline__ void split2(float x0, float x1, uint32_t& h, uint32_t& l) {
    __nv_bfloat162 hh = __floats2bfloat162_rn(x0, x1);
    h = *(uint32_t*)&hh;
    float h0 = __uint_as_float(h << 16);
    float h1 = __uint_as_float(h & 0xFFFF0000u);
    __nv_bfloat162 ll = __floats2bfloat162_rn(x0 - h0, x1 - h1);
    l = *(uint32_t*)&ll;
}
__device__ __forceinline__ void split2h(float x0, float x1, uint32_t& h, uint32_t& l) {
    __half2 hh = __floats2half2_rn(x0, x1);
    h = *(uint32_t*)&hh;
    float2 hf = __half22float2(hh);
    __half2 ll = __floats2half2_rn(x0 - hf.x, x1 - hf.y);
    l = *(uint32_t*)&ll;
}
__device__ __forceinline__ uint32_t packh(float x0, float x1) {
    __half2 hh = __floats2half2_rn(x0, x1);
    return *(uint32_t*)&hh;
}
__device__ __forceinline__ void mma_bf16(float* d, const uint32_t* a, uint32_t b0, uint32_t b1) {
    asm volatile(
        "mma.sync.aligned.m16n8k16.row.col.f32.bf16.bf16.f32 "
        "{%0,%1,%2,%3}, {%4,%5,%6,%7}, {%8,%9}, {%0,%1,%2,%3};"
        : "+f"(d[0]), "+f"(d[1]), "+f"(d[2]), "+f"(d[3])
        : "r"(a[0]), "r"(a[1]), "r"(a[2]), "r"(a[3]), "r"(b0), "r"(b1));
}
__device__ __forceinline__ void mma_fp16(float* d, const uint32_t* a, uint32_t b0, uint32_t b1) {
    asm volatile(
        "mma.sync.aligned.m16n8k16.row.col.f32.f16.f16.f32 "
        "{%0,%1,%2,%3}, {%4,%5,%6,%7}, {%8,%9}, {%0,%1,%2,%3};"
        : "+f"(d[0]), "+f"(d[1]), "+f"(d[2]), "+f"(d[3])
        : "r"(a[0]), "r"(a[1]), "r"(a[2]), "r"(a[3]), "r"(b0), "r"(b1));
}
__device__ __forceinline__ void ldmx4(uint32_t* r, uint32_t addr) {
    asm volatile("ldmatrix.sync.aligned.m8n8.x4.shared.b16 {%0,%1,%2,%3}, [%4];"
                 : "=r"(r[0]), "=r"(r[1]), "=r"(r[2]), "=r"(r[3]) : "r"(addr));
}
__device__ __forceinline__ void ldmx4t(uint32_t* r, uint32_t addr) {
    asm volatile("ldmatrix.sync.aligned.m8n8.x4.trans.shared.b16 {%0,%1,%2,%3}, [%4];"
                 : "=r"(r[0]), "=r"(r[1]), "=r"(r[2]), "=r"(r[3]) : "r"(addr));
}
__device__ __forceinline__ void cpa16(uint32_t s, const void* g) {
    asm volatile("cp.async.cg.shared.global [%0], [%1], 16;" :: "r"(s), "l"(g));
}
__device__ __forceinline__ void cpa_commit() {
    asm volatile("cp.async.commit_group;" ::: "memory");
}
template <int N>
__device__ __forceinline__ void cpa_wait() {
    asm volatile("cp.async.wait_group %0;" :: "n"(N) : "memory");
}
__device__ __forceinline__ uint32_t ofs64(int r, int k) {
    return (uint32_t)(r * 64 + k * 2) ^ (uint32_t)(((r >> 1) & 3) << 4);
}
__device__ __forceinline__ uint32_t ofs128(int r, int k) {
    return (uint32_t)(r * 128 + k * 2) ^ (uint32_t)((r & 7) << 4);
}
__device__ __forceinline__ uint32_t ofs256(int r, int k) {
    return (uint32_t)(r * 256 + k * 2) ^ (uint32_t)((r & 7) << 4);
}

// ---------------------------------------------------------------------------
__global__ __launch_bounds__(256) void k0_wt(const float* __restrict__ W) {
    __shared__ float tile[32][33];
    int n0 = blockIdx.x * 32, h0 = blockIdx.y * 32;
    int tx = threadIdx.x & 31, ty = threadIdx.x >> 5;
    #pragma unroll
    for (int r = 0; r < 4; r++) {
        int h = h0 + ty + r * 8;
        float v = W[(size_t)h * K2 + n0 + tx];
        tile[ty + r * 8][tx] = v;
        g_W16[(size_t)h * K2 + n0 + tx] = __float2half_rn(v);
    }
    __syncthreads();
    #pragma unroll
    for (int r = 0; r < 4; r++) {
        int n = n0 + ty + r * 8;
        float x = tile[tx][ty + r * 8];
        __nv_bfloat16 h = __float2bfloat16_rn(x);
        g_Wt_h[(size_t)n * HD + h0 + tx] = h;
        g_Wt_l[(size_t)n * HD + h0 + tx] = __float2bfloat16_rn(x - __bfloat162float(h));
    }
}

__global__ __launch_bounds__(256) void k_zero() {
    size_t i = ((size_t)blockIdx.x * 256 + threadIdx.x) * 4;
    *(float4*)(g_ctx2f + i) = make_float4(0.f, 0.f, 0.f, 0.f);
}

__global__ __launch_bounds__(256) void k_bh(const float* __restrict__ hidden,
                                            const float* __restrict__ bias) {
    int w = (blockIdx.x * 256 + threadIdx.x) >> 5;
    int lane = threadIdx.x & 31;
    int b = w >> 6, l = w & 63;
    const float* hrow = hidden + (l * BB + b) * HD;
    float s = 0.f;
    for (int h = lane; h < HD; h += 32) s += bias[h] * hrow[h];
    #pragma unroll
    for (int o = 16; o; o >>= 1) s += __shfl_xor_sync(0xffffffffu, s, o);
    if (lane == 0) g_bh[w] = s;
}

// ---------------------------------------------------------------------------
// K1 v2 (mma, bf16 3-term): Wh[m,n] = hidden_row(m) . Wt[n]; emit fp16 hi/lo.
// grid (32,8)=256 CTAs, 256 thr, 2 CTAs/SM. 8 warps = 2 kg (K=512) x 4 wm (16m).
// B (Wt bf16 hi/lo) cp.async tile (kg,p) at (kg*2+p)*8192 (ofs64, 64n x 32k).
// A direct LDG fp32 + bf16 split2. kg-split-2 reduction in acc [64m][68] @ 0.
// ---------------------------------------------------------------------------
__global__ __launch_bounds__(256, 2) void k1_mma(const float* __restrict__ hidden) {
    extern __shared__ __align__(128) uint8_t sm[];
    const int tid = threadIdx.x, w = tid >> 5, lane = tid & 31;
    const int grp = lane >> 2, tig = lane & 3;
    const int by = blockIdx.y;                // batch
    const int n0 = blockIdx.x * 64;
    const int kg = w >> 2, wm = w & 3, m0w = wm * 16;
    uint32_t sb = smem_u32(sm);

    const int tg = tid >> 7, si = tid & 127;
    const int brow = si >> 1, part = si & 1;
    const uint32_t bd0 = ofs64(brow, part * 16), bd1 = ofs64(brow, part * 16 + 8);

    auto stage = [&](int c, int p) {
        uint32_t base = sb + (uint32_t)(tg * 2 + p) * 8192;
        size_t go = (size_t)(n0 + brow) * HD + tg * 512 + c * 32 + part * 16;
        cpa16(base + bd0, g_Wt_h + go);
        cpa16(base + bd1, g_Wt_h + go + 8);
        cpa16(base + 4096 + bd0, g_Wt_l + go);
        cpa16(base + 4096 + bd1, g_Wt_l + go + 8);
    };
    stage(0, 0);
    cpa_commit();

    float d[8][4];
    #pragma unroll
    for (int i = 0; i < 8; i++) { d[i][0]=d[i][1]=d[i][2]=d[i][3]=0.f; }

    const int l = m0w + grp;                  // 0..63 within batch
    const float* arow0 = hidden + (size_t)(l * BB + by) * HD + kg * 512 + tig * 2;
    const float* arow1 = arow0 + (size_t)8 * BB * HD;

    for (int c = 0; c < 16; c++) {
        int p = c & 1;
        cpa_wait<0>();
        __syncthreads();
        if (c < 15) { stage(c + 1, p ^ 1); cpa_commit(); }
        uint32_t bbase = sb + (uint32_t)(kg * 2 + p) * 8192;
        #pragma unroll
        for (int ks = 0; ks < 2; ks++) {
            const float* a0 = arow0 + c * 32 + ks * 16;
            const float* a1 = arow1 + c * 32 + ks * 16;
            float2 v0 = *(const float2*)(a0);
            float2 v1 = *(const float2*)(a1);
            float2 v2 = *(const float2*)(a0 + 8);
            float2 v3 = *(const float2*)(a1 + 8);
            uint32_t ah[4], al[4];
            split2(v0.x, v0.y, ah[0], al[0]);
            split2(v1.x, v1.y, ah[1], al[1]);
            split2(v2.x, v2.y, ah[2], al[2]);
            split2(v3.x, v3.y, ah[3], al[3]);
            int bcol = ks * 16 + (lane & 8);
            int br = (lane & 7) + ((lane >> 1) & 8);
            uint32_t bh4[4][4], bl4[4][4];
            #pragma unroll
            for (int nb = 0; nb < 4; nb++) {
                uint32_t addr = bbase + ofs64(nb * 16 + br, bcol);
                ldmx4(bh4[nb], addr);
                ldmx4(bl4[nb], addr + 4096);
            }
            #pragma unroll
            for (int nb = 0; nb < 4; nb++) {
                mma_bf16(d[2*nb],   ah, bh4[nb][0], bh4[nb][1]);
                mma_bf16(d[2*nb+1], ah, bh4[nb][2], bh4[nb][3]);
            }
            #pragma unroll
            for (int nb = 0; nb < 4; nb++) {
                mma_bf16(d[2*nb],   al, bh4[nb][0], bh4[nb][1]);
                mma_bf16(d[2*nb+1], al, bh4[nb][2], bh4[nb][3]);
            }
            #pragma unroll
            for (int nb = 0; nb < 4; nb++) {
                mma_bf16(d[2*nb],   ah, bl4[nb][0], bl4[nb][1]);
                mma_bf16(d[2*nb+1], ah, bl4[nb][2], bl4[nb][3]);
            }
        }
    }

    __syncthreads();
    float* acc = (float*)sm;   // [64][68]
    if (kg == 1) {
        #pragma unroll
        for (int nt = 0; nt < 8; nt++) {
            int cl = nt * 8 + tig * 2;
            *(float2*)&acc[l * 68 + cl]       = make_float2(d[nt][0], d[nt][1]);
            *(float2*)&acc[(l + 8) * 68 + cl] = make_float2(d[nt][2], d[nt][3]);
        }
    }
    __syncthreads();
    if (kg == 0) {
        #pragma unroll
        for (int nt = 0; nt < 8; nt++) {
            int cl = nt * 8 + tig * 2;
            float2 o0 = *(const float2*)&acc[l * 68 + cl];
            float2 o1 = *(const float2*)&acc[(l + 8) * 68 + cl];
            float x0 = d[nt][0] + o0.x, x1 = d[nt][1] + o0.y;
            float y0 = d[nt][2] + o1.x, y1 = d[nt][3] + o1.y;
            uint32_t h01, l01, h23, l23;
            split2h(x0, x1, h01, l01);
            split2h(y0, y1, h23, l23);
            size_t rA = (size_t)(by * 64 + l) * K2 + n0 + cl;
            size_t rB = rA + (size_t)8 * K2;
            *(uint32_t*)(g_Wh_h + rA) = h01;
            *(uint32_t*)(g_Wh_l + rA) = l01;
            *(uint32_t*)(g_Wh_h + rB) = h23;
            *(uint32_t*)(g_Wh_l + rB) = l23;
        }
    }
}

// ---------------------------------------------------------------------------
// K2 v4 (mma, fp16 3-term) — frozen at HMMA floor.
// ---------------------------------------------------------------------------
__global__ __launch_bounds__(256, 2) void k2_mma(const float* __restrict__ enc) {
    extern __shared__ __align__(128) uint8_t sm[];
    const int tid = threadIdx.x, w = tid >> 5, lane = tid & 31;
    const int grp = lane >> 2, tig = lane & 3;
    const int b = blockIdx.y, sBlk = blockIdx.x * 128;
    const int kg = w >> 2, ws = w & 3, sW = ws * 32;
    uint32_t sb = smem_u32(sm);
    const float* encb = enc + (size_t)b * SS * K2;
    const __half* Bhp = g_Wh_h + (size_t)b * 64 * K2;
    const __half* Blp = g_Wh_l + (size_t)b * 64 * K2;

    const int tg = tid >> 7, si = tid & 127;
    const int brow = si >> 1, part = si & 1;
    const uint32_t bd0 = ofs64(brow, part * 16), bd1 = ofs64(brow, part * 16 + 8);

    auto stage = [&](int c, int p) {
        uint32_t base = sb + (uint32_t)(tg * 2 + p) * 8192;
        size_t go = (size_t)brow * K2 + tg * 1024 + c * 32 + part * 16;
        cpa16(base + bd0, Bhp + go);
        cpa16(base + bd1, Bhp + go + 8);
        cpa16(base + 4096 + bd0, Blp + go);
        cpa16(base + 4096 + bd1, Blp + go + 8);
    };

    stage(0, 0);
    cpa_commit();

    float d[2][8][4];
    #pragma unroll
    for (int i = 0; i < 2; i++)
        #pragma unroll
        for (int j = 0; j < 8; j++) { d[i][j][0]=d[i][j][1]=d[i][j][2]=d[i][j][3]=0.f; }

    const float* arow0 = encb + (size_t)(sBlk + sW + grp) * K2 + kg * 1024 + tig * 2;

    for (int c = 0; c < 32; c++) {
        int p = c & 1;
        cpa_wait<0>();
        __syncthreads();
        if (c < 31) { stage(c + 1, p ^ 1); cpa_commit(); }
        uint32_t bbase = sb + (uint32_t)(kg * 2 + p) * 8192;
        #pragma unroll
        for (int ks = 0; ks < 2; ks++) {
            const float* a0 = arow0 + c * 32 + ks * 16;
            float2 u0 = *(const float2*)(a0);
            float2 u1 = *(const float2*)(a0 + 8 * K2);
            float2 u2 = *(const float2*)(a0 + 8);
            float2 u3 = *(const float2*)(a0 + 8 * K2 + 8);
            float2 w0 = *(const float2*)(a0 + 16 * K2);
            float2 w1 = *(const float2*)(a0 + 24 * K2);
            float2 w2 = *(const float2*)(a0 + 16 * K2 + 8);
            float2 w3 = *(const float2*)(a0 + 24 * K2 + 8);
            uint32_t ahA[4], alA[4], ahB[4], alB[4];
            split2h(u0.x, u0.y, ahA[0], alA[0]);
            split2h(u1.x, u1.y, ahA[1], alA[1]);
            split2h(u2.x, u2.y, ahA[2], alA[2]);
            split2h(u3.x, u3.y, ahA[3], alA[3]);
            split2h(w0.x, w0.y, ahB[0], alB[0]);
            split2h(w1.x, w1.y, ahB[1], alB[1]);
            split2h(w2.x, w2.y, ahB[2], alB[2]);
            split2h(w3.x, w3.y, ahB[3], alB[3]);
            int bcol = ks * 16 + (lane & 8);
            int br = (lane & 7) + ((lane >> 1) & 8);
            #pragma unroll
            for (int hf = 0; hf < 2; hf++) {
                uint32_t bh4[2][4], bl4[2][4];
                #pragma unroll
                for (int q = 0; q < 2; q++) {
                    int nb = hf * 2 + q;
                    uint32_t addr = bbase + ofs64(nb * 16 + br, bcol);
                    ldmx4(bh4[q], addr);
                    ldmx4(bl4[q], addr + 4096);
                }
                #pragma unroll
                for (int q = 0; q < 2; q++) {
                    mma_fp16(d[0][hf*4 + q*2],     ahA, bh4[q][0], bh4[q][1]);
                    mma_fp16(d[0][hf*4 + q*2 + 1], ahA, bh4[q][2], bh4[q][3]);
                    mma_fp16(d[1][hf*4 + q*2],     ahB, bh4[q][0], bh4[q][1]);
                    mma_fp16(d[1][hf*4 + q*2 + 1], ahB, bh4[q][2], bh4[q][3]);
                }
                #pragma unroll
                for (int q = 0; q < 2; q++) {
                    mma_fp16(d[0][hf*4 + q*2],     alA, bh4[q][0], bh4[q][1]);
                    mma_fp16(d[0][hf*4 + q*2 + 1], alA, bh4[q][2], bh4[q][3]);
                    mma_fp16(d[1][hf*4 + q*2],     alB, bh4[q][0], bh4[q][1]);
                    mma_fp16(d[1][hf*4 + q*2 + 1], alB, bh4[q][2], bh4[q][3]);
                }
                #pragma unroll
                for (int q = 0; q < 2; q++) {
                    mma_fp16(d[0][hf*4 + q*2],     ahA, bl4[q][0], bl4[q][1]);
                    mma_fp16(d[0][hf*4 + q*2 + 1], ahA, bl4[q][2], bl4[q][3]);
                    mma_fp16(d[1][hf*4 + q*2],     ahB, bl4[q][0], bl4[q][1]);
                    mma_fp16(d[1][hf*4 + q*2 + 1], ahB, bl4[q][2], bl4[q][3]);
                }
            }
        }
    }

    __syncthreads();
    float* acc = (float*)sm;
    if (kg == 1) {
        #pragma unroll
        for (int mb = 0; mb < 2; mb++)
            #pragma unroll
            for (int nb = 0; nb < 8; nb++) {
                int sl = sW + mb * 16 + grp;
                int cl = nb * 8 + tig * 2;
                *(float2*)&acc[sl * 68 + cl]       = make_float2(d[mb][nb][0], d[mb][nb][1]);
                *(float2*)&acc[(sl + 8) * 68 + cl] = make_float2(d[mb][nb][2], d[mb][nb][3]);
            }
    }
    __syncthreads();
    if (kg == 0) {
        #pragma unroll
        for (int mb = 0; mb < 2; mb++)
            #pragma unroll
            for (int nb = 0; nb < 8; nb++) {
                int sl = sW + mb * 16 + grp;
                int cl = nb * 8 + tig * 2;
                float b0v = g_bh[b * 64 + cl], b1v = g_bh[b * 64 + cl + 1];
                float2 o0 = *(const float2*)&acc[sl * 68 + cl];
                float2 o1 = *(const float2*)&acc[(sl + 8) * 68 + cl];
                size_t q0 = (size_t)(b * 64 + cl) * SS + sBlk, q1 = q0 + SS;
                g_scores[q0 + sl]     = d[mb][nb][0] + o0.x + b0v;
                g_scores[q1 + sl]     = d[mb][nb][1] + o0.y + b1v;
                g_scores[q0 + sl + 8] = d[mb][nb][2] + o1.x + b0v;
                g_scores[q1 + sl + 8] = d[mb][nb][3] + o1.y + b1v;
            }
    }
}

// ---------------------------------------------------------------------------
__global__ __launch_bounds__(256) void k3a() {
    int row = blockIdx.x, t = threadIdx.x;
    const float4* p = (const float4*)(g_scores + (size_t)row * SS) + t;
    float4 v[4];
    #pragma unroll
    for (int i = 0; i < 4; i++) v[i] = p[i * 256];
    float m = -1e30f;
    #pragma unroll
    for (int i = 0; i < 4; i++)
        m = fmaxf(m, fmaxf(fmaxf(v[i].x, v[i].y), fmaxf(v[i].z, v[i].w)));
    __shared__ float red[256];
    red[t] = m; __syncthreads();
    #pragma unroll
    for (int o = 128; o; o >>= 1) { if (t < o) red[t] = fmaxf(red[t], red[t + o]); __syncthreads(); }
    m = red[0]; __syncthreads();
    float s = 0.f;
    #pragma unroll
    for (int i = 0; i < 4; i++)
        s += expf(v[i].x - m) + expf(v[i].y - m) + expf(v[i].z - m) + expf(v[i].w - m);
    red[t] = s; __syncthreads();
    #pragma unroll
    for (int o = 128; o; o >>= 1) { if (t < o) red[t] += red[t + o]; __syncthreads(); }
    if (t == 0) { g_m[row] = m; g_inv[row] = 1.f / red[0]; }
}

__global__ __launch_bounds__(256) void k3b(float* __restrict__ out_w) {
    int b = blockIdx.y, s0 = blockIdx.x * 128;
    int t = threadIdx.x, l = t >> 2, q = t & 3;
    int row = b * 64 + l;
    float m = g_m[row], inv = g_inv[row];
    int sb0 = s0 + q * 32;
    const float* p = g_scores + (size_t)row * SS + sb0;
    uint32_t hb[16], lb[16];
    #pragma unroll
    for (int j = 0; j < 16; j++) {
        float2 x = *(const float2*)(p + j * 2);
        float w0 = expf(x.x - m) * inv;
        float w1 = expf(x.y - m) * inv;
        out_w[((size_t)b * SS + sb0 + j * 2) * LL + l]     = w0;
        out_w[((size_t)b * SS + sb0 + j * 2 + 1) * LL + l] = w1;
        split2h(w0, w1, hb[j], lb[j]);
    }
    size_t wo = (size_t)row * SS + sb0;
    #pragma unroll
    for (int j = 0; j < 4; j++) {
        *(uint4*)(g_w_h + wo + j * 8) = make_uint4(hb[4*j], hb[4*j+1], hb[4*j+2], hb[4*j+3]);
        *(uint4*)(g_w_l + wo + j * 8) = make_uint4(lb[4*j], lb[4*j+1], lb[4*j+2], lb[4*j+3]);
    }
}

// ---------------------------------------------------------------------------
// K4 v2 (mma, fp16 1-term): ctx2[l,k] = sum_s w_hi[l,s] enc_hi[s,k]
// (R13 structure; trailing per-chunk sync removed, one sync added post-loop)
// ---------------------------------------------------------------------------
__global__ __launch_bounds__(256, 2) void k4_mma(const float* __restrict__ enc) {
    extern __shared__ __align__(128) uint8_t sm[];
    const int tid = threadIdx.x, w = tid >> 5, lane = tid & 31;
    const int grp = lane >> 2, tig = lane & 3;
    const int wk = w & 3, sg = w >> 2;
    const int b = blockIdx.y;
    const int kb0 = (blockIdx.x & 15) * 128;
    const int sh0 = (blockIdx.x >> 4) * 2048;
    const int m0w = wk * 32;
    uint32_t sb = smem_u32(sm);
    const float* encb = enc + (size_t)b * SS * K2;
    const __half* Bh = g_w_h + (size_t)b * 64 * SS;

    const int as = tid >> 2, akp = (tid & 3) * 32;
    const int brow = tid >> 2, bso = (tid & 3) * 16;

    uint32_t ph[16];
    uint4 pb0, pb1;
    auto ldg = [&](int c) {
        int s0 = sh0 + c * 64;
        const float* ap = encb + (size_t)(s0 + as) * K2 + kb0 + akp;
        #pragma unroll
        for (int j = 0; j < 8; j++) {
            float4 v = *(const float4*)(ap + j * 4);
            ph[j*2]   = packh(v.x, v.y);
            ph[j*2+1] = packh(v.z, v.w);
        }
        const __half* bp = Bh + (size_t)brow * SS + s0 + bso;
        pb0 = *(const uint4*)(bp);
        pb1 = *(const uint4*)(bp + 8);
    };
    auto sts = [&](int p) {
        uint32_t ab = (uint32_t)p * 16384;
        *(uint4*)(sm + ab + ofs256(as, akp))      = make_uint4(ph[0], ph[1], ph[2], ph[3]);
        *(uint4*)(sm + ab + ofs256(as, akp + 8))  = make_uint4(ph[4], ph[5], ph[6], ph[7]);
        *(uint4*)(sm + ab + ofs256(as, akp + 16)) = make_uint4(ph[8], ph[9], ph[10], ph[11]);
        *(uint4*)(sm + ab + ofs256(as, akp + 24)) = make_uint4(ph[12], ph[13], ph[14], ph[15]);
        uint32_t bb = 32768u + (uint32_t)p * 8192;
        *(uint4*)(sm + bb + ofs128(brow, bso))     = pb0;
        *(uint4*)(sm + bb + ofs128(brow, bso + 8)) = pb1;
    };

    float d[2][8][4];
    #pragma unroll
    for (int i = 0; i < 2; i++)
        #pragma unroll
        for (int j = 0; j < 8; j++) { d[i][j][0]=d[i][j][1]=d[i][j][2]=d[i][j][3]=0.f; }

    ldg(0);
    for (int c = 0; c < 32; c++) {
        int p = c & 1;
        sts(p);
        __syncthreads();
        if (c < 31) ldg(c + 1);
        uint32_t ab = sb + (uint32_t)p * 16384;
        uint32_t bb = sb + 32768u + (uint32_t)p * 8192;
        #pragma unroll
        for (int j = 0; j < 2; j++) {
            int ks = sg * 2 + j;
            int srow = ks * 16 + (lane & 7) + ((lane >> 4) & 1) * 8;
            int mcb  = ((lane >> 3) & 1) * 8;
            uint32_t a0[4], a1[4];
            ldmx4t(a0, ab + ofs256(srow, m0w + mcb));
            ldmx4t(a1, ab + ofs256(srow, m0w + 16 + mcb));
            int bcol = ks * 16 + (lane & 8);
            int br = (lane & 7) + ((lane >> 1) & 8);
            uint32_t bh4[4][4];
            #pragma unroll
            for (int np = 0; np < 4; np++)
                ldmx4(bh4[np], bb + ofs128(np * 16 + br, bcol));
            #pragma unroll
            for (int np = 0; np < 4; np++) {
                mma_fp16(d[0][2*np],   a0, bh4[np][0], bh4[np][1]);
                mma_fp16(d[0][2*np+1], a0, bh4[np][2], bh4[np][3]);
                mma_fp16(d[1][2*np],   a1, bh4[np][0], bh4[np][1]);
                mma_fp16(d[1][2*np+1], a1, bh4[np][2], bh4[np][3]);
            }
        }
    }
    __syncthreads();

    float* acc = (float*)sm;
    if (sg == 1) {
        #pragma unroll
        for (int mb = 0; mb < 2; mb++)
            #pragma unroll
            for (int nb = 0; nb < 8; nb++) {
                int k0 = m0w + mb * 16 + grp;
                int c0 = nb * 8 + tig * 2;
                acc[k0 * 67 + c0]           = d[mb][nb][0];
                acc[k0 * 67 + c0 + 1]       = d[mb][nb][1];
                acc[(k0 + 8) * 67 + c0]     = d[mb][nb][2];
                acc[(k0 + 8) * 67 + c0 + 1] = d[mb][nb][3];
            }
    }
    __syncthreads();
    if (sg == 0) {
        #pragma unroll
        for (int mb = 0; mb < 2; mb++)
            #pragma unroll
            for (int nb = 0; nb < 8; nb++) {
                int k0 = m0w + mb * 16 + grp;
                int c0 = nb * 8 + tig * 2;
                acc[k0 * 67 + c0]           += d[mb][nb][0];
                acc[k0 * 67 + c0 + 1]       += d[mb][nb][1];
                acc[(k0 + 8) * 67 + c0]     += d[mb][nb][2];
                acc[(k0 + 8) * 67 + c0 + 1] += d[mb][nb][3];
            }
    }
    __syncthreads();
    {
        int l = tid >> 2, kq = (tid & 3) * 32;
        float* dst = g_ctx2f + (size_t)(b * 64 + l) * K2 + kb0 + kq;
        #pragma unroll
        for (int j = 0; j < 32; j++)
            atomicAdd(dst + j, acc[(kq + j) * 67 + l]);
    }
}

// ---------------------------------------------------------------------------
__global__ __launch_bounds__(256) void k5_mma(const float* __restrict__ bias,
                                              float* __restrict__ out) {
    const int tid = threadIdx.x, w = tid >> 5, lane = tid & 31;
    const int grp = lane >> 2, tig = lane & 3;
    const int m0 = blockIdx.y * 128 + w * 16;
    const int n0 = blockIdx.x * 32;
    int mA = m0 + grp, mB = mA + 8;
    const float* a0p = g_ctx2f + (size_t)mA * K2 + tig * 2;
    const float* a1p = g_ctx2f + (size_t)mB * K2 + tig * 2;

    float d[4][4];
    #pragma unroll
    for (int i = 0; i < 4; i++) { d[i][0]=d[i][1]=d[i][2]=d[i][3]=0.f; }

    #pragma unroll 2
    for (int k0 = 0; k0 < K2; k0 += 16) {
        float2 v0 = *(const float2*)(a0p + k0);
        float2 v1 = *(const float2*)(a1p + k0);
        float2 v2 = *(const float2*)(a0p + k0 + 8);
        float2 v3 = *(const float2*)(a1p + k0 + 8);
        uint32_t ah[4], al[4];
        split2h(v0.x, v0.y, ah[0], al[0]);
        split2h(v1.x, v1.y, ah[1], al[1]);
        split2h(v2.x, v2.y, ah[2], al[2]);
        split2h(v3.x, v3.y, ah[3], al[3]);
        uint32_t bh0[4], bh1[4];
        #pragma unroll
        for (int nt = 0; nt < 4; nt++) {
            const __half* wp = g_W16 + (size_t)(n0 + nt * 8 + grp) * K2 + k0 + 2 * tig;
            bh0[nt] = *(const uint32_t*)(wp);
            bh1[nt] = *(const uint32_t*)(wp + 8);
        }
        #pragma unroll
        for (int nt = 0; nt < 4; nt++) mma_fp16(d[nt], ah, bh0[nt], bh1[nt]);
        #pragma unroll
        for (int nt = 0; nt < 4; nt++) mma_fp16(d[nt], al, bh0[nt], bh1[nt]);
    }
    #pragma unroll
    for (int nt = 0; nt < 4; nt++) {
        int hp = n0 + nt * 8 + tig * 2;
        float2 bv = *(const float2*)(bias + hp);
        float2 o0 = {d[nt][0] + bv.x, d[nt][1] + bv.y};
        float2 o1 = {d[nt][2] + bv.x, d[nt][3] + bv.y};
        *(float2*)(out + (size_t)mA * HD + hp) = o0;
        *(float2*)(out + (size_t)mB * HD + hp) = o1;
    }
}

// ---------------------------------------------------------------------------
extern "C" void kernel_launch(void* const* d_in, const int* in_sizes, int n_in,
                              void* d_out, int out_size) {
    (void)in_sizes; (void)n_in; (void)out_size;
    const float* hidden = (const float*)d_in[0];
    const float* enc    = (const float*)d_in[1];
    const float* W      = (const float*)d_in[2];
    const float* bias   = (const float*)d_in[3];
    float* out_ctx = (float*)d_out;
    float* out_w   = (float*)d_out + (size_t)BB * LL * HD;

    const int SM1 = 32768;
    const int SM2 = 34816;
    const int SM4 = 49152;
    cudaFuncSetAttribute(k2_mma, cudaFuncAttributeMaxDynamicSharedMemorySize, SM2);
    cudaFuncSetAttribute(k4_mma, cudaFuncAttributeMaxDynamicSharedMemorySize, SM4);

    k0_wt<<<dim3(64, 32), 256>>>(W);
    k_zero<<<1024, 256>>>();
    k_bh<<<64, 256>>>(hidden, bias);
    k1_mma<<<dim3(32, 8), 256, SM1>>>(hidden);
    k2_mma<<<dim3(32, 8), 256, SM2>>>(enc);
    k3a<<<512, 256>>>();
    k3b<<<dim3(32, 8), 256>>>(out_w);
    k4_mma<<<dim3(32, 8), 256, SM4>>>(enc);
    k5_mma<<<dim3(32, 4), 256>>>(bias, out_ctx);
}

// round 15
// speedup vs baseline: 1.2320x; 1.2199x over previous
#include <cuda_runtime.h>
#include <cuda_bf16.h>
#include <cuda_fp16.h>
#include <math.h>
#include <stdint.h>

#define HD   1024
#define K2   2048
#define BB   8
#define SS   4096
#define LL   64
#define M512 (BB*LL)

// ---- device scratch ----
__device__ __nv_bfloat16 g_Wt_h[K2 * HD];
__device__ __nv_bfloat16 g_Wt_l[K2 * HD];
__device__ __half        g_W16[HD * K2];
__device__ __half        g_Wh_h[M512 * K2];
__device__ __half        g_Wh_l[M512 * K2];
__device__ float         g_bh[M512];
__device__ float         g_scores[(size_t)M512 * SS];
__device__ float         g_m[M512];
__device__ float         g_inv[M512];
__device__ float         g_ctx2f[M512 * K2];

// ---- helpers ----
__device__ __forceinline__ uint32_t smem_u32(const void* p) {
    uint32_t a;
    asm("{ .reg .u64 t; cvta.to.shared.u64 t, %1; cvt.u32.u64 %0, t; }" : "=r"(a) : "l"(p));
    return a;
}
__device__ __forceinline__ void split2(float x0, float x1, uint32_t& h, uint32_t& l) {
    __nv_bfloat162 hh = __floats2bfloat162_rn(x0, x1);
    h = *(uint32_t*)&hh;
    float h0 = __uint_as_float(h << 16);
    float h1 = __uint_as_float(h & 0xFFFF0000u);
    __nv_bfloat162 ll = __floats2bfloat162_rn(x0 - h0, x1 - h1);
    l = *(uint32_t*)&ll;
}
__device__ __forceinline__ void split2h(float x0, float x1, uint32_t& h, uint32_t& l) {
    __half2 hh = __floats2half2_rn(x0, x1);
    h = *(uint32_t*)&hh;
    float2 hf = __half22float2(hh);
    __half2 ll = __floats2half2_rn(x0 - hf.x, x1 - hf.y);
    l = *(uint32_t*)&ll;
}
__device__ __forceinline__ void mma_bf16(float* d, const uint32_t* a, uint32_t b0, uint32_t b1) {
    asm volatile(
        "mma.sync.aligned.m16n8k16.row.col.f32.bf16.bf16.f32 "
        "{%0,%1,%2,%3}, {%4,%5,%6,%7}, {%8,%9}, {%0,%1,%2,%3};"
        : "+f"(d[0]), "+f"(d[1]), "+f"(d[2]), "+f"(d[3])
        : "r"(a[0]), "r"(a[1]), "r"(a[2]), "r"(a[3]), "r"(b0), "r"(b1));
}
__device__ __forceinline__ void mma_fp16(float* d, const uint32_t* a, uint32_t b0, uint32_t b1) {
    asm volatile(
        "mma.sync.aligned.m16n8k16.row.col.f32.f16.f16.f32 "
        "{%0,%1,%2,%3}, {%4,%5,%6,%7}, {%8,%9}, {%0,%1,%2,%3};"
        : "+f"(d[0]), "+f"(d[1]), "+f"(d[2]), "+f"(d[3])
        : "r"(a[0]), "r"(a[1]), "r"(a[2]), "r"(a[3]), "r"(b0), "r"(b1));
}
__device__ __forceinline__ void ldmx4(uint32_t* r, uint32_t addr) {
    asm volatile("ldmatrix.sync.aligned.m8n8.x4.shared.b16 {%0,%1,%2,%3}, [%4];"
                 : "=r"(r[0]), "=r"(r[1]), "=r"(r[2]), "=r"(r[3]) : "r"(addr));
}
__device__ __forceinline__ void cpa16(uint32_t s, const void* g) {
    asm volatile("cp.async.cg.shared.global [%0], [%1], 16;" :: "r"(s), "l"(g));
}
__device__ __forceinline__ void cpa_commit() {
    asm volatile("cp.async.commit_group;" ::: "memory");
}
template <int N>
__device__ __forceinline__ void cpa_wait() {
    asm volatile("cp.async.wait_group %0;" :: "n"(N) : "memory");
}
__device__ __forceinline__ uint32_t ofs64(int r, int k) {
    return (uint32_t)(r * 64 + k * 2) ^ (uint32_t)(((r >> 1) & 3) << 4);
}

// ---------------------------------------------------------------------------
__global__ __launch_bounds__(256) void k0_wt(const float* __restrict__ W) {
    __shared__ float tile[32][33];
    int n0 = blockIdx.x * 32, h0 = blockIdx.y * 32;
    int tx = threadIdx.x & 31, ty = threadIdx.x >> 5;
    #pragma unroll
    for (int r = 0; r < 4; r++) {
        int h = h0 + ty + r * 8;
        float v = W[(size_t)h * K2 + n0 + tx];
        tile[ty + r * 8][tx] = v;
        g_W16[(size_t)h * K2 + n0 + tx] = __float2half_rn(v);
    }
    __syncthreads();
    #pragma unroll
    for (int r = 0; r < 4; r++) {
        int n = n0 + ty + r * 8;
        float x = tile[tx][ty + r * 8];
        __nv_bfloat16 h = __float2bfloat16_rn(x);
        g_Wt_h[(size_t)n * HD + h0 + tx] = h;
        g_Wt_l[(size_t)n * HD + h0 + tx] = __float2bfloat16_rn(x - __bfloat162float(h));
    }
}

__global__ __launch_bounds__(256) void k_bh(const float* __restrict__ hidden,
                                            const float* __restrict__ bias) {
    int w = (blockIdx.x * 256 + threadIdx.x) >> 5;
    int lane = threadIdx.x & 31;
    int b = w >> 6, l = w & 63;
    const float* hrow = hidden + (l * BB + b) * HD;
    float s = 0.f;
    for (int h = lane; h < HD; h += 32) s += bias[h] * hrow[h];
    #pragma unroll
    for (int o = 16; o; o >>= 1) s += __shfl_xor_sync(0xffffffffu, s, o);
    if (lane == 0) g_bh[w] = s;
}

// ---------------------------------------------------------------------------
// K1 v2 (mma, bf16 3-term): Wh[m,n] = hidden_row(m) . Wt[n]; emit fp16 hi/lo.
// ---------------------------------------------------------------------------
__global__ __launch_bounds__(256, 2) void k1_mma(const float* __restrict__ hidden) {
    extern __shared__ __align__(128) uint8_t sm[];
    const int tid = threadIdx.x, w = tid >> 5, lane = tid & 31;
    const int grp = lane >> 2, tig = lane & 3;
    const int by = blockIdx.y;
    const int n0 = blockIdx.x * 64;
    const int kg = w >> 2, wm = w & 3, m0w = wm * 16;
    uint32_t sb = smem_u32(sm);

    const int tg = tid >> 7, si = tid & 127;
    const int brow = si >> 1, part = si & 1;
    const uint32_t bd0 = ofs64(brow, part * 16), bd1 = ofs64(brow, part * 16 + 8);

    auto stage = [&](int c, int p) {
        uint32_t base = sb + (uint32_t)(tg * 2 + p) * 8192;
        size_t go = (size_t)(n0 + brow) * HD + tg * 512 + c * 32 + part * 16;
        cpa16(base + bd0, g_Wt_h + go);
        cpa16(base + bd1, g_Wt_h + go + 8);
        cpa16(base + 4096 + bd0, g_Wt_l + go);
        cpa16(base + 4096 + bd1, g_Wt_l + go + 8);
    };
    stage(0, 0);
    cpa_commit();

    float d[8][4];
    #pragma unroll
    for (int i = 0; i < 8; i++) { d[i][0]=d[i][1]=d[i][2]=d[i][3]=0.f; }

    const int l = m0w + grp;
    const float* arow0 = hidden + (size_t)(l * BB + by) * HD + kg * 512 + tig * 2;
    const float* arow1 = arow0 + (size_t)8 * BB * HD;

    for (int c = 0; c < 16; c++) {
        int p = c & 1;
        cpa_wait<0>();
        __syncthreads();
        if (c < 15) { stage(c + 1, p ^ 1); cpa_commit(); }
        uint32_t bbase = sb + (uint32_t)(kg * 2 + p) * 8192;
        #pragma unroll
        for (int ks = 0; ks < 2; ks++) {
            const float* a0 = arow0 + c * 32 + ks * 16;
            const float* a1 = arow1 + c * 32 + ks * 16;
            float2 v0 = *(const float2*)(a0);
            float2 v1 = *(const float2*)(a1);
            float2 v2 = *(const float2*)(a0 + 8);
            float2 v3 = *(const float2*)(a1 + 8);
            uint32_t ah[4], al[4];
            split2(v0.x, v0.y, ah[0], al[0]);
            split2(v1.x, v1.y, ah[1], al[1]);
            split2(v2.x, v2.y, ah[2], al[2]);
            split2(v3.x, v3.y, ah[3], al[3]);
            int bcol = ks * 16 + (lane & 8);
            int br = (lane & 7) + ((lane >> 1) & 8);
            uint32_t bh4[4][4], bl4[4][4];
            #pragma unroll
            for (int nb = 0; nb < 4; nb++) {
                uint32_t addr = bbase + ofs64(nb * 16 + br, bcol);
                ldmx4(bh4[nb], addr);
                ldmx4(bl4[nb], addr + 4096);
            }
            #pragma unroll
            for (int nb = 0; nb < 4; nb++) {
                mma_bf16(d[2*nb],   ah, bh4[nb][0], bh4[nb][1]);
                mma_bf16(d[2*nb+1], ah, bh4[nb][2], bh4[nb][3]);
            }
            #pragma unroll
            for (int nb = 0; nb < 4; nb++) {
                mma_bf16(d[2*nb],   al, bh4[nb][0], bh4[nb][1]);
                mma_bf16(d[2*nb+1], al, bh4[nb][2], bh4[nb][3]);
            }
            #pragma unroll
            for (int nb = 0; nb < 4; nb++) {
                mma_bf16(d[2*nb],   ah, bl4[nb][0], bl4[nb][1]);
                mma_bf16(d[2*nb+1], ah, bl4[nb][2], bl4[nb][3]);
            }
        }
    }

    __syncthreads();
    float* acc = (float*)sm;
    if (kg == 1) {
        #pragma unroll
        for (int nt = 0; nt < 8; nt++) {
            int cl = nt * 8 + tig * 2;
            *(float2*)&acc[l * 68 + cl]       = make_float2(d[nt][0], d[nt][1]);
            *(float2*)&acc[(l + 8) * 68 + cl] = make_float2(d[nt][2], d[nt][3]);
        }
    }
    __syncthreads();
    if (kg == 0) {
        #pragma unroll
        for (int nt = 0; nt < 8; nt++) {
            int cl = nt * 8 + tig * 2;
            float2 o0 = *(const float2*)&acc[l * 68 + cl];
            float2 o1 = *(const float2*)&acc[(l + 8) * 68 + cl];
            float x0 = d[nt][0] + o0.x, x1 = d[nt][1] + o0.y;
            float y0 = d[nt][2] + o1.x, y1 = d[nt][3] + o1.y;
            uint32_t h01, l01, h23, l23;
            split2h(x0, x1, h01, l01);
            split2h(y0, y1, h23, l23);
            size_t rA = (size_t)(by * 64 + l) * K2 + n0 + cl;
            size_t rB = rA + (size_t)8 * K2;
            *(uint32_t*)(g_Wh_h + rA) = h01;
            *(uint32_t*)(g_Wh_l + rA) = l01;
            *(uint32_t*)(g_Wh_h + rB) = h23;
            *(uint32_t*)(g_Wh_l + rB) = l23;
        }
    }
}

// ---------------------------------------------------------------------------
// K2 v4 (mma, fp16 3-term) — frozen.
// ---------------------------------------------------------------------------
__global__ __launch_bounds__(256, 2) void k2_mma(const float* __restrict__ enc) {
    extern __shared__ __align__(128) uint8_t sm[];
    const int tid = threadIdx.x, w = tid >> 5, lane = tid & 31;
    const int grp = lane >> 2, tig = lane & 3;
    const int b = blockIdx.y, sBlk = blockIdx.x * 128;
    const int kg = w >> 2, ws = w & 3, sW = ws * 32;
    uint32_t sb = smem_u32(sm);
    const float* encb = enc + (size_t)b * SS * K2;
    const __half* Bhp = g_Wh_h + (size_t)b * 64 * K2;
    const __half* Blp = g_Wh_l + (size_t)b * 64 * K2;

    const int tg = tid >> 7, si = tid & 127;
    const int brow = si >> 1, part = si & 1;
    const uint32_t bd0 = ofs64(brow, part * 16), bd1 = ofs64(brow, part * 16 + 8);

    auto stage = [&](int c, int p) {
        uint32_t base = sb + (uint32_t)(tg * 2 + p) * 8192;
        size_t go = (size_t)brow * K2 + tg * 1024 + c * 32 + part * 16;
        cpa16(base + bd0, Bhp + go);
        cpa16(base + bd1, Bhp + go + 8);
        cpa16(base + 4096 + bd0, Blp + go);
        cpa16(base + 4096 + bd1, Blp + go + 8);
    };

    stage(0, 0);
    cpa_commit();

    float d[2][8][4];
    #pragma unroll
    for (int i = 0; i < 2; i++)
        #pragma unroll
        for (int j = 0; j < 8; j++) { d[i][j][0]=d[i][j][1]=d[i][j][2]=d[i][j][3]=0.f; }

    const float* arow0 = encb + (size_t)(sBlk + sW + grp) * K2 + kg * 1024 + tig * 2;

    for (int c = 0; c < 32; c++) {
        int p = c & 1;
        cpa_wait<0>();
        __syncthreads();
        if (c < 31) { stage(c + 1, p ^ 1); cpa_commit(); }
        uint32_t bbase = sb + (uint32_t)(kg * 2 + p) * 8192;
        #pragma unroll
        for (int ks = 0; ks < 2; ks++) {
            const float* a0 = arow0 + c * 32 + ks * 16;
            float2 u0 = *(const float2*)(a0);
            float2 u1 = *(const float2*)(a0 + 8 * K2);
            float2 u2 = *(const float2*)(a0 + 8);
            float2 u3 = *(const float2*)(a0 + 8 * K2 + 8);
            float2 w0 = *(const float2*)(a0 + 16 * K2);
            float2 w1 = *(const float2*)(a0 + 24 * K2);
            float2 w2 = *(const float2*)(a0 + 16 * K2 + 8);
            float2 w3 = *(const float2*)(a0 + 24 * K2 + 8);
            uint32_t ahA[4], alA[4], ahB[4], alB[4];
            split2h(u0.x, u0.y, ahA[0], alA[0]);
            split2h(u1.x, u1.y, ahA[1], alA[1]);
            split2h(u2.x, u2.y, ahA[2], alA[2]);
            split2h(u3.x, u3.y, ahA[3], alA[3]);
            split2h(w0.x, w0.y, ahB[0], alB[0]);
            split2h(w1.x, w1.y, ahB[1], alB[1]);
            split2h(w2.x, w2.y, ahB[2], alB[2]);
            split2h(w3.x, w3.y, ahB[3], alB[3]);
            int bcol = ks * 16 + (lane & 8);
            int br = (lane & 7) + ((lane >> 1) & 8);
            #pragma unroll
            for (int hf = 0; hf < 2; hf++) {
                uint32_t bh4[2][4], bl4[2][4];
                #pragma unroll
                for (int q = 0; q < 2; q++) {
                    int nb = hf * 2 + q;
                    uint32_t addr = bbase + ofs64(nb * 16 + br, bcol);
                    ldmx4(bh4[q], addr);
                    ldmx4(bl4[q], addr + 4096);
                }
                #pragma unroll
                for (int q = 0; q < 2; q++) {
                    mma_fp16(d[0][hf*4 + q*2],     ahA, bh4[q][0], bh4[q][1]);
                    mma_fp16(d[0][hf*4 + q*2 + 1], ahA, bh4[q][2], bh4[q][3]);
                    mma_fp16(d[1][hf*4 + q*2],     ahB, bh4[q][0], bh4[q][1]);
                    mma_fp16(d[1][hf*4 + q*2 + 1], ahB, bh4[q][2], bh4[q][3]);
                }
                #pragma unroll
                for (int q = 0; q < 2; q++) {
                    mma_fp16(d[0][hf*4 + q*2],     alA, bh4[q][0], bh4[q][1]);
                    mma_fp16(d[0][hf*4 + q*2 + 1], alA, bh4[q][2], bh4[q][3]);
                    mma_fp16(d[1][hf*4 + q*2],     alB, bh4[q][0], bh4[q][1]);
                    mma_fp16(d[1][hf*4 + q*2 + 1], alB, bh4[q][2], bh4[q][3]);
                }
                #pragma unroll
                for (int q = 0; q < 2; q++) {
                    mma_fp16(d[0][hf*4 + q*2],     ahA, bl4[q][0], bl4[q][1]);
                    mma_fp16(d[0][hf*4 + q*2 + 1], ahA, bl4[q][2], bl4[q][3]);
                    mma_fp16(d[1][hf*4 + q*2],     ahB, bl4[q][0], bl4[q][1]);
                    mma_fp16(d[1][hf*4 + q*2 + 1], ahB, bl4[q][2], bl4[q][3]);
                }
            }
        }
    }

    __syncthreads();
    float* acc = (float*)sm;
    if (kg == 1) {
        #pragma unroll
        for (int mb = 0; mb < 2; mb++)
            #pragma unroll
            for (int nb = 0; nb < 8; nb++) {
                int sl = sW + mb * 16 + grp;
                int cl = nb * 8 + tig * 2;
                *(float2*)&acc[sl * 68 + cl]       = make_float2(d[mb][nb][0], d[mb][nb][1]);
                *(float2*)&acc[(sl + 8) * 68 + cl] = make_float2(d[mb][nb][2], d[mb][nb][3]);
            }
    }
    __syncthreads();
    if (kg == 0) {
        #pragma unroll
        for (int mb = 0; mb < 2; mb++)
            #pragma unroll
            for (int nb = 0; nb < 8; nb++) {
                int sl = sW + mb * 16 + grp;
                int cl = nb * 8 + tig * 2;
                float b0v = g_bh[b * 64 + cl], b1v = g_bh[b * 64 + cl + 1];
                float2 o0 = *(const float2*)&acc[sl * 68 + cl];
                float2 o1 = *(const float2*)&acc[(sl + 8) * 68 + cl];
                size_t q0 = (size_t)(b * 64 + cl) * SS + sBlk, q1 = q0 + SS;
                g_scores[q0 + sl]     = d[mb][nb][0] + o0.x + b0v;
                g_scores[q1 + sl]     = d[mb][nb][1] + o0.y + b1v;
                g_scores[q0 + sl + 8] = d[mb][nb][2] + o1.x + b0v;
                g_scores[q1 + sl + 8] = d[mb][nb][3] + o1.y + b1v;
            }
    }
}

// ---------------------------------------------------------------------------
__global__ __launch_bounds__(256) void k3a() {
    int row = blockIdx.x, t = threadIdx.x;
    const float4* p = (const float4*)(g_scores + (size_t)row * SS) + t;
    float4 v[4];
    #pragma unroll
    for (int i = 0; i < 4; i++) v[i] = p[i * 256];
    float m = -1e30f;
    #pragma unroll
    for (int i = 0; i < 4; i++)
        m = fmaxf(m, fmaxf(fmaxf(v[i].x, v[i].y), fmaxf(v[i].z, v[i].w)));
    __shared__ float red[256];
    red[t] = m; __syncthreads();
    #pragma unroll
    for (int o = 128; o; o >>= 1) { if (t < o) red[t] = fmaxf(red[t], red[t + o]); __syncthreads(); }
    m = red[0]; __syncthreads();
    float s = 0.f;
    #pragma unroll
    for (int i = 0; i < 4; i++)
        s += expf(v[i].x - m) + expf(v[i].y - m) + expf(v[i].z - m) + expf(v[i].w - m);
    red[t] = s; __syncthreads();
    #pragma unroll
    for (int o = 128; o; o >>= 1) { if (t < o) red[t] += red[t + o]; __syncthreads(); }
    if (t == 0) { g_m[row] = m; g_inv[row] = 1.f / red[0]; }
}

// K3b: weights -> out_w [B,S,L] (coalesced) only
__global__ __launch_bounds__(256) void k3b(float* __restrict__ out_w) {
    int b = blockIdx.y, s0 = blockIdx.x * 128;
    int t = threadIdx.x, l = t >> 2, q = t & 3;
    int row = b * 64 + l;
    float m = g_m[row], inv = g_inv[row];
    int sb0 = s0 + q * 32;
    const float* p = g_scores + (size_t)row * SS + sb0;
    #pragma unroll
    for (int j = 0; j < 16; j++) {
        float2 x = *(const float2*)(p + j * 2);
        float w0 = expf(x.x - m) * inv;
        float w1 = expf(x.y - m) * inv;
        out_w[((size_t)b * SS + sb0 + j * 2) * LL + l]     = w0;
        out_w[((size_t)b * SS + sb0 + j * 2 + 1) * LL + l] = w1;
    }
}

// ---------------------------------------------------------------------------
// K4 sparse: ctx2[row,:] = sum over survivors (w >= 1e-10) of w * enc[s,:]
// One CTA per (b,l) row; deterministic ascending-s order; exact fp32.
// ---------------------------------------------------------------------------
__global__ __launch_bounds__(256) void k4_sparse(const float* __restrict__ enc) {
    const int row = blockIdx.x;
    const int b = row >> 6;
    const int t = threadIdx.x;
    const float* srow = g_scores + (size_t)row * SS;
    const float* encb = enc + (size_t)b * SS * K2;
    const float m = g_m[row], inv = g_inv[row];

    float acc[8];
    #pragma unroll
    for (int i = 0; i < 8; i++) acc[i] = 0.f;

    __shared__ int   ls[256];
    __shared__ float lw[256];
    __shared__ int   wcnt[8];
    __shared__ int   woff[9];

    for (int pass = 0; pass < 16; pass++) {
        int s = pass * 256 + t;
        float w = expf(srow[s] - m) * inv;
        bool keep = (w >= 1e-10f);
        unsigned mk = __ballot_sync(0xffffffffu, keep);
        if ((t & 31) == 0) wcnt[t >> 5] = __popc(mk);
        __syncthreads();
        if (t == 0) {
            int o = 0;
            #pragma unroll
            for (int i = 0; i < 8; i++) { woff[i] = o; o += wcnt[i]; }
            woff[8] = o;
        }
        __syncthreads();
        int cnt = woff[8];
        if (cnt > 0) {
            if (keep) {
                int pos = woff[t >> 5] + __popc(mk & ((1u << (t & 31)) - 1u));
                ls[pos] = s;
                lw[pos] = w;
            }
            __syncthreads();
            for (int e = 0; e < cnt; e++) {
                int   se = ls[e];
                float we = lw[e];
                const float* erow = encb + (size_t)se * K2 + t;
                #pragma unroll
                for (int i = 0; i < 8; i++) acc[i] = fmaf(we, erow[i * 256], acc[i]);
            }
        }
        __syncthreads();
    }
    float* dst = g_ctx2f + (size_t)row * K2 + t;
    #pragma unroll
    for (int i = 0; i < 8; i++) dst[i * 256] = acc[i];
}

// ---------------------------------------------------------------------------
// K5 (mma, fp16 2-term): out[m,h] = bias[h] + sum_k ctx2[m,k] W[h,k]
// ---------------------------------------------------------------------------
__global__ __launch_bounds__(256) void k5_mma(const float* __restrict__ bias,
                                              float* __restrict__ out) {
    const int tid = threadIdx.x, w = tid >> 5, lane = tid & 31;
    const int grp = lane >> 2, tig = lane & 3;
    const int m0 = blockIdx.y * 128 + w * 16;
    const int n0 = blockIdx.x * 32;
    int mA = m0 + grp, mB = mA + 8;
    const float* a0p = g_ctx2f + (size_t)mA * K2 + tig * 2;
    const float* a1p = g_ctx2f + (size_t)mB * K2 + tig * 2;

    float d[4][4];
    #pragma unroll
    for (int i = 0; i < 4; i++) { d[i][0]=d[i][1]=d[i][2]=d[i][3]=0.f; }

    #pragma unroll 2
    for (int k0 = 0; k0 < K2; k0 += 16) {
        float2 v0 = *(const float2*)(a0p + k0);
        float2 v1 = *(const float2*)(a1p + k0);
        float2 v2 = *(const float2*)(a0p + k0 + 8);
        float2 v3 = *(const float2*)(a1p + k0 + 8);
        uint32_t ah[4], al[4];
        split2h(v0.x, v0.y, ah[0], al[0]);
        split2h(v1.x, v1.y, ah[1], al[1]);
        split2h(v2.x, v2.y, ah[2], al[2]);
        split2h(v3.x, v3.y, ah[3], al[3]);
        uint32_t bh0[4], bh1[4];
        #pragma unroll
        for (int nt = 0; nt < 4; nt++) {
            const __half* wp = g_W16 + (size_t)(n0 + nt * 8 + grp) * K2 + k0 + 2 * tig;
            bh0[nt] = *(const uint32_t*)(wp);
            bh1[nt] = *(const uint32_t*)(wp + 8);
        }
        #pragma unroll
        for (int nt = 0; nt < 4; nt++) mma_fp16(d[nt], ah, bh0[nt], bh1[nt]);
        #pragma unroll
        for (int nt = 0; nt < 4; nt++) mma_fp16(d[nt], al, bh0[nt], bh1[nt]);
    }
    #pragma unroll
    for (int nt = 0; nt < 4; nt++) {
        int hp = n0 + nt * 8 + tig * 2;
        float2 bv = *(const float2*)(bias + hp);
        float2 o0 = {d[nt][0] + bv.x, d[nt][1] + bv.y};
        float2 o1 = {d[nt][2] + bv.x, d[nt][3] + bv.y};
        *(float2*)(out + (size_t)mA * HD + hp) = o0;
        *(float2*)(out + (size_t)mB * HD + hp) = o1;
    }
}

// ---------------------------------------------------------------------------
extern "C" void kernel_launch(void* const* d_in, const int* in_sizes, int n_in,
                              void* d_out, int out_size) {
    (void)in_sizes; (void)n_in; (void)out_size;
    const float* hidden = (const float*)d_in[0];
    const float* enc    = (const float*)d_in[1];
    const float* W      = (const float*)d_in[2];
    const float* bias   = (const float*)d_in[3];
    float* out_ctx = (float*)d_out;
    float* out_w   = (float*)d_out + (size_t)BB * LL * HD;

    const int SM1 = 32768;
    const int SM2 = 34816;
    cudaFuncSetAttribute(k2_mma, cudaFuncAttributeMaxDynamicSharedMemorySize, SM2);

    k0_wt<<<dim3(64, 32), 256>>>(W);
    k_bh<<<64, 256>>>(hidden, bias);
    k1_mma<<<dim3(32, 8), 256, SM1>>>(hidden);
    k2_mma<<<dim3(32, 8), 256, SM2>>>(enc);
    k3a<<<512, 256>>>();
    k3b<<<dim3(32, 8), 256>>>(out_w);
    k4_sparse<<<512, 256>>>(enc);
    k5_mma<<<dim3(32, 4), 256>>>(bias, out_ctx);
}

// round 16
// speedup vs baseline: 1.3878x; 1.1264x over previous
#include <cuda_runtime.h>
#include <cuda_bf16.h>
#include <cuda_fp16.h>
#include <math.h>
#include <stdint.h>

#define HD   1024
#define K2   2048
#define BB   8
#define SS   4096
#define LL   64
#define M512 (BB*LL)

// ---- device scratch ----
__device__ __nv_bfloat16 g_Wt_h[K2 * HD];
__device__ __nv_bfloat16 g_Wt_l[K2 * HD];
__device__ __half        g_W16[HD * K2];
__device__ __half        g_Wh_h[M512 * K2];
__device__ __half        g_Wh_l[M512 * K2];
__device__ float         g_bh[M512];
__device__ float         g_scores[(size_t)M512 * SS];
__device__ float         g_m[M512];
__device__ float         g_inv[M512];
__device__ float         g_ctx2f[M512 * K2];

// ---- helpers ----
__device__ __forceinline__ uint32_t smem_u32(const void* p) {
    uint32_t a;
    asm("{ .reg .u64 t; cvta.to.shared.u64 t, %1; cvt.u32.u64 %0, t; }" : "=r"(a) : "l"(p));
    return a;
}
__device__ __forceinline__ void split2(float x0, float x1, uint32_t& h, uint32_t& l) {
    __nv_bfloat162 hh = __floats2bfloat162_rn(x0, x1);
    h = *(uint32_t*)&hh;
    float h0 = __uint_as_float(h << 16);
    float h1 = __uint_as_float(h & 0xFFFF0000u);
    __nv_bfloat162 ll = __floats2bfloat162_rn(x0 - h0, x1 - h1);
    l = *(uint32_t*)&ll;
}
__device__ __forceinline__ void split2h(float x0, float x1, uint32_t& h, uint32_t& l) {
    __half2 hh = __floats2half2_rn(x0, x1);
    h = *(uint32_t*)&hh;
    float2 hf = __half22float2(hh);
    __half2 ll = __floats2half2_rn(x0 - hf.x, x1 - hf.y);
    l = *(uint32_t*)&ll;
}
__device__ __forceinline__ void mma_bf16(float* d, const uint32_t* a, uint32_t b0, uint32_t b1) {
    asm volatile(
        "mma.sync.aligned.m16n8k16.row.col.f32.bf16.bf16.f32 "
        "{%0,%1,%2,%3}, {%4,%5,%6,%7}, {%8,%9}, {%0,%1,%2,%3};"
        : "+f"(d[0]), "+f"(d[1]), "+f"(d[2]), "+f"(d[3])
        : "r"(a[0]), "r"(a[1]), "r"(a[2]), "r"(a[3]), "r"(b0), "r"(b1));
}
__device__ __forceinline__ void mma_fp16(float* d, const uint32_t* a, uint32_t b0, uint32_t b1) {
    asm volatile(
        "mma.sync.aligned.m16n8k16.row.col.f32.f16.f16.f32 "
        "{%0,%1,%2,%3}, {%4,%5,%6,%7}, {%8,%9}, {%0,%1,%2,%3};"
        : "+f"(d[0]), "+f"(d[1]), "+f"(d[2]), "+f"(d[3])
        : "r"(a[0]), "r"(a[1]), "r"(a[2]), "r"(a[3]), "r"(b0), "r"(b1));
}
__device__ __forceinline__ void ldmx4(uint32_t* r, uint32_t addr) {
    asm volatile("ldmatrix.sync.aligned.m8n8.x4.shared.b16 {%0,%1,%2,%3}, [%4];"
                 : "=r"(r[0]), "=r"(r[1]), "=r"(r[2]), "=r"(r[3]) : "r"(addr));
}
__device__ __forceinline__ void cpa16(uint32_t s, const void* g) {
    asm volatile("cp.async.cg.shared.global [%0], [%1], 16;" :: "r"(s), "l"(g));
}
__device__ __forceinline__ void cpa_commit() {
    asm volatile("cp.async.commit_group;" ::: "memory");
}
template <int N>
__device__ __forceinline__ void cpa_wait() {
    asm volatile("cp.async.wait_group %0;" :: "n"(N) : "memory");
}
__device__ __forceinline__ uint32_t ofs64(int r, int k) {
    return (uint32_t)(r * 64 + k * 2) ^ (uint32_t)(((r >> 1) & 3) << 4);
}

// ---------------------------------------------------------------------------
__global__ __launch_bounds__(256) void k0_wt(const float* __restrict__ W) {
    __shared__ float tile[32][33];
    int n0 = blockIdx.x * 32, h0 = blockIdx.y * 32;
    int tx = threadIdx.x & 31, ty = threadIdx.x >> 5;
    #pragma unroll
    for (int r = 0; r < 4; r++) {
        int h = h0 + ty + r * 8;
        float v = W[(size_t)h * K2 + n0 + tx];
        tile[ty + r * 8][tx] = v;
        g_W16[(size_t)h * K2 + n0 + tx] = __float2half_rn(v);
    }
    __syncthreads();
    #pragma unroll
    for (int r = 0; r < 4; r++) {
        int n = n0 + ty + r * 8;
        float x = tile[tx][ty + r * 8];
        __nv_bfloat16 h = __float2bfloat16_rn(x);
        g_Wt_h[(size_t)n * HD + h0 + tx] = h;
        g_Wt_l[(size_t)n * HD + h0 + tx] = __float2bfloat16_rn(x - __bfloat162float(h));
    }
}

__global__ __launch_bounds__(256) void k_bh(const float* __restrict__ hidden,
                                            const float* __restrict__ bias) {
    int w = (blockIdx.x * 256 + threadIdx.x) >> 5;
    int lane = threadIdx.x & 31;
    int b = w >> 6, l = w & 63;
    const float* hrow = hidden + (l * BB + b) * HD;
    float s = 0.f;
    for (int h = lane; h < HD; h += 32) s += bias[h] * hrow[h];
    #pragma unroll
    for (int o = 16; o; o >>= 1) s += __shfl_xor_sync(0xffffffffu, s, o);
    if (lane == 0) g_bh[w] = s;
}

// ---------------------------------------------------------------------------
// K1 v2 (mma, bf16 3-term): Wh[m,n] = hidden_row(m) . Wt[n]; emit fp16 hi/lo.
// ---------------------------------------------------------------------------
__global__ __launch_bounds__(256, 2) void k1_mma(const float* __restrict__ hidden) {
    extern __shared__ __align__(128) uint8_t sm[];
    const int tid = threadIdx.x, w = tid >> 5, lane = tid & 31;
    const int grp = lane >> 2, tig = lane & 3;
    const int by = blockIdx.y;
    const int n0 = blockIdx.x * 64;
    const int kg = w >> 2, wm = w & 3, m0w = wm * 16;
    uint32_t sb = smem_u32(sm);

    const int tg = tid >> 7, si = tid & 127;
    const int brow = si >> 1, part = si & 1;
    const uint32_t bd0 = ofs64(brow, part * 16), bd1 = ofs64(brow, part * 16 + 8);

    auto stage = [&](int c, int p) {
        uint32_t base = sb + (uint32_t)(tg * 2 + p) * 8192;
        size_t go = (size_t)(n0 + brow) * HD + tg * 512 + c * 32 + part * 16;
        cpa16(base + bd0, g_Wt_h + go);
        cpa16(base + bd1, g_Wt_h + go + 8);
        cpa16(base + 4096 + bd0, g_Wt_l + go);
        cpa16(base + 4096 + bd1, g_Wt_l + go + 8);
    };
    stage(0, 0);
    cpa_commit();

    float d[8][4];
    #pragma unroll
    for (int i = 0; i < 8; i++) { d[i][0]=d[i][1]=d[i][2]=d[i][3]=0.f; }

    const int l = m0w + grp;
    const float* arow0 = hidden + (size_t)(l * BB + by) * HD + kg * 512 + tig * 2;
    const float* arow1 = arow0 + (size_t)8 * BB * HD;

    for (int c = 0; c < 16; c++) {
        int p = c & 1;
        cpa_wait<0>();
        __syncthreads();
        if (c < 15) { stage(c + 1, p ^ 1); cpa_commit(); }
        uint32_t bbase = sb + (uint32_t)(kg * 2 + p) * 8192;
        #pragma unroll
        for (int ks = 0; ks < 2; ks++) {
            const float* a0 = arow0 + c * 32 + ks * 16;
            const float* a1 = arow1 + c * 32 + ks * 16;
            float2 v0 = *(const float2*)(a0);
            float2 v1 = *(const float2*)(a1);
            float2 v2 = *(const float2*)(a0 + 8);
            float2 v3 = *(const float2*)(a1 + 8);
            uint32_t ah[4], al[4];
            split2(v0.x, v0.y, ah[0], al[0]);
            split2(v1.x, v1.y, ah[1], al[1]);
            split2(v2.x, v2.y, ah[2], al[2]);
            split2(v3.x, v3.y, ah[3], al[3]);
            int bcol = ks * 16 + (lane & 8);
            int br = (lane & 7) + ((lane >> 1) & 8);
            uint32_t bh4[4][4], bl4[4][4];
            #pragma unroll
            for (int nb = 0; nb < 4; nb++) {
                uint32_t addr = bbase + ofs64(nb * 16 + br, bcol);
                ldmx4(bh4[nb], addr);
                ldmx4(bl4[nb], addr + 4096);
            }
            #pragma unroll
            for (int nb = 0; nb < 4; nb++) {
                mma_bf16(d[2*nb],   ah, bh4[nb][0], bh4[nb][1]);
                mma_bf16(d[2*nb+1], ah, bh4[nb][2], bh4[nb][3]);
            }
            #pragma unroll
            for (int nb = 0; nb < 4; nb++) {
                mma_bf16(d[2*nb],   al, bh4[nb][0], bh4[nb][1]);
                mma_bf16(d[2*nb+1], al, bh4[nb][2], bh4[nb][3]);
            }
            #pragma unroll
            for (int nb = 0; nb < 4; nb++) {
                mma_bf16(d[2*nb],   ah, bl4[nb][0], bl4[nb][1]);
                mma_bf16(d[2*nb+1], ah, bl4[nb][2], bl4[nb][3]);
            }
        }
    }

    __syncthreads();
    float* acc = (float*)sm;
    if (kg == 1) {
        #pragma unroll
        for (int nt = 0; nt < 8; nt++) {
            int cl = nt * 8 + tig * 2;
            *(float2*)&acc[l * 68 + cl]       = make_float2(d[nt][0], d[nt][1]);
            *(float2*)&acc[(l + 8) * 68 + cl] = make_float2(d[nt][2], d[nt][3]);
        }
    }
    __syncthreads();
    if (kg == 0) {
        #pragma unroll
        for (int nt = 0; nt < 8; nt++) {
            int cl = nt * 8 + tig * 2;
            float2 o0 = *(const float2*)&acc[l * 68 + cl];
            float2 o1 = *(const float2*)&acc[(l + 8) * 68 + cl];
            float x0 = d[nt][0] + o0.x, x1 = d[nt][1] + o0.y;
            float y0 = d[nt][2] + o1.x, y1 = d[nt][3] + o1.y;
            uint32_t h01, l01, h23, l23;
            split2h(x0, x1, h01, l01);
            split2h(y0, y1, h23, l23);
            size_t rA = (size_t)(by * 64 + l) * K2 + n0 + cl;
            size_t rB = rA + (size_t)8 * K2;
            *(uint32_t*)(g_Wh_h + rA) = h01;
            *(uint32_t*)(g_Wh_l + rA) = l01;
            *(uint32_t*)(g_Wh_h + rB) = h23;
            *(uint32_t*)(g_Wh_l + rB) = l23;
        }
    }
}

// ---------------------------------------------------------------------------
// K2 v4 (mma, fp16 3-term) — frozen.
// ---------------------------------------------------------------------------
__global__ __launch_bounds__(256, 2) void k2_mma(const float* __restrict__ enc) {
    extern __shared__ __align__(128) uint8_t sm[];
    const int tid = threadIdx.x, w = tid >> 5, lane = tid & 31;
    const int grp = lane >> 2, tig = lane & 3;
    const int b = blockIdx.y, sBlk = blockIdx.x * 128;
    const int kg = w >> 2, ws = w & 3, sW = ws * 32;
    uint32_t sb = smem_u32(sm);
    const float* encb = enc + (size_t)b * SS * K2;
    const __half* Bhp = g_Wh_h + (size_t)b * 64 * K2;
    const __half* Blp = g_Wh_l + (size_t)b * 64 * K2;

    const int tg = tid >> 7, si = tid & 127;
    const int brow = si >> 1, part = si & 1;
    const uint32_t bd0 = ofs64(brow, part * 16), bd1 = ofs64(brow, part * 16 + 8);

    auto stage = [&](int c, int p) {
        uint32_t base = sb + (uint32_t)(tg * 2 + p) * 8192;
        size_t go = (size_t)brow * K2 + tg * 1024 + c * 32 + part * 16;
        cpa16(base + bd0, Bhp + go);
        cpa16(base + bd1, Bhp + go + 8);
        cpa16(base + 4096 + bd0, Blp + go);
        cpa16(base + 4096 + bd1, Blp + go + 8);
    };

    stage(0, 0);
    cpa_commit();

    float d[2][8][4];
    #pragma unroll
    for (int i = 0; i < 2; i++)
        #pragma unroll
        for (int j = 0; j < 8; j++) { d[i][j][0]=d[i][j][1]=d[i][j][2]=d[i][j][3]=0.f; }

    const float* arow0 = encb + (size_t)(sBlk + sW + grp) * K2 + kg * 1024 + tig * 2;

    for (int c = 0; c < 32; c++) {
        int p = c & 1;
        cpa_wait<0>();
        __syncthreads();
        if (c < 31) { stage(c + 1, p ^ 1); cpa_commit(); }
        uint32_t bbase = sb + (uint32_t)(kg * 2 + p) * 8192;
        #pragma unroll
        for (int ks = 0; ks < 2; ks++) {
            const float* a0 = arow0 + c * 32 + ks * 16;
            float2 u0 = *(const float2*)(a0);
            float2 u1 = *(const float2*)(a0 + 8 * K2);
            float2 u2 = *(const float2*)(a0 + 8);
            float2 u3 = *(const float2*)(a0 + 8 * K2 + 8);
            float2 w0 = *(const float2*)(a0 + 16 * K2);
            float2 w1 = *(const float2*)(a0 + 24 * K2);
            float2 w2 = *(const float2*)(a0 + 16 * K2 + 8);
            float2 w3 = *(const float2*)(a0 + 24 * K2 + 8);
            uint32_t ahA[4], alA[4], ahB[4], alB[4];
            split2h(u0.x, u0.y, ahA[0], alA[0]);
            split2h(u1.x, u1.y, ahA[1], alA[1]);
            split2h(u2.x, u2.y, ahA[2], alA[2]);
            split2h(u3.x, u3.y, ahA[3], alA[3]);
            split2h(w0.x, w0.y, ahB[0], alB[0]);
            split2h(w1.x, w1.y, ahB[1], alB[1]);
            split2h(w2.x, w2.y, ahB[2], alB[2]);
            split2h(w3.x, w3.y, ahB[3], alB[3]);
            int bcol = ks * 16 + (lane & 8);
            int br = (lane & 7) + ((lane >> 1) & 8);
            #pragma unroll
            for (int hf = 0; hf < 2; hf++) {
                uint32_t bh4[2][4], bl4[2][4];
                #pragma unroll
                for (int q = 0; q < 2; q++) {
                    int nb = hf * 2 + q;
                    uint32_t addr = bbase + ofs64(nb * 16 + br, bcol);
                    ldmx4(bh4[q], addr);
                    ldmx4(bl4[q], addr + 4096);
                }
                #pragma unroll
                for (int q = 0; q < 2; q++) {
                    mma_fp16(d[0][hf*4 + q*2],     ahA, bh4[q][0], bh4[q][1]);
                    mma_fp16(d[0][hf*4 + q*2 + 1], ahA, bh4[q][2], bh4[q][3]);
                    mma_fp16(d[1][hf*4 + q*2],     ahB, bh4[q][0], bh4[q][1]);
                    mma_fp16(d[1][hf*4 + q*2 + 1], ahB, bh4[q][2], bh4[q][3]);
                }
                #pragma unroll
                for (int q = 0; q < 2; q++) {
                    mma_fp16(d[0][hf*4 + q*2],     alA, bh4[q][0], bh4[q][1]);
                    mma_fp16(d[0][hf*4 + q*2 + 1], alA, bh4[q][2], bh4[q][3]);
                    mma_fp16(d[1][hf*4 + q*2],     alB, bh4[q][0], bh4[q][1]);
                    mma_fp16(d[1][hf*4 + q*2 + 1], alB, bh4[q][2], bh4[q][3]);
                }
                #pragma unroll
                for (int q = 0; q < 2; q++) {
                    mma_fp16(d[0][hf*4 + q*2],     ahA, bl4[q][0], bl4[q][1]);
                    mma_fp16(d[0][hf*4 + q*2 + 1], ahA, bl4[q][2], bl4[q][3]);
                    mma_fp16(d[1][hf*4 + q*2],     ahB, bl4[q][0], bl4[q][1]);
                    mma_fp16(d[1][hf*4 + q*2 + 1], ahB, bl4[q][2], bl4[q][3]);
                }
            }
        }
    }

    __syncthreads();
    float* acc = (float*)sm;
    if (kg == 1) {
        #pragma unroll
        for (int mb = 0; mb < 2; mb++)
            #pragma unroll
            for (int nb = 0; nb < 8; nb++) {
                int sl = sW + mb * 16 + grp;
                int cl = nb * 8 + tig * 2;
                *(float2*)&acc[sl * 68 + cl]       = make_float2(d[mb][nb][0], d[mb][nb][1]);
                *(float2*)&acc[(sl + 8) * 68 + cl] = make_float2(d[mb][nb][2], d[mb][nb][3]);
            }
    }
    __syncthreads();
    if (kg == 0) {
        #pragma unroll
        for (int mb = 0; mb < 2; mb++)
            #pragma unroll
            for (int nb = 0; nb < 8; nb++) {
                int sl = sW + mb * 16 + grp;
                int cl = nb * 8 + tig * 2;
                float b0v = g_bh[b * 64 + cl], b1v = g_bh[b * 64 + cl + 1];
                float2 o0 = *(const float2*)&acc[sl * 68 + cl];
                float2 o1 = *(const float2*)&acc[(sl + 8) * 68 + cl];
                size_t q0 = (size_t)(b * 64 + cl) * SS + sBlk, q1 = q0 + SS;
                g_scores[q0 + sl]     = d[mb][nb][0] + o0.x + b0v;
                g_scores[q1 + sl]     = d[mb][nb][1] + o0.y + b1v;
                g_scores[q0 + sl + 8] = d[mb][nb][2] + o1.x + b0v;
                g_scores[q1 + sl + 8] = d[mb][nb][3] + o1.y + b1v;
            }
    }
}

// ---------------------------------------------------------------------------
// K4 sparse v2 (absorbs k3a): computes m/inv, writes them, then
// ctx2[row,:] = sum over survivors (w >= 1e-10) of w * enc[s,:]  (exact fp32)
// ---------------------------------------------------------------------------
__global__ __launch_bounds__(256) void k4_sparse(const float* __restrict__ enc) {
    const int row = blockIdx.x;
    const int b = row >> 6;
    const int t = threadIdx.x;
    const float* srow = g_scores + (size_t)row * SS;
    const float* encb = enc + (size_t)b * SS * K2;

    float v[16];
    #pragma unroll
    for (int i = 0; i < 16; i++) v[i] = srow[i * 256 + t];

    __shared__ float red[256];
    float m = -1e30f;
    #pragma unroll
    for (int i = 0; i < 16; i++) m = fmaxf(m, v[i]);
    red[t] = m; __syncthreads();
    #pragma unroll
    for (int o = 128; o; o >>= 1) { if (t < o) red[t] = fmaxf(red[t], red[t + o]); __syncthreads(); }
    m = red[0]; __syncthreads();
    float s = 0.f;
    #pragma unroll
    for (int i = 0; i < 16; i++) { v[i] = expf(v[i] - m); s += v[i]; }
    red[t] = s; __syncthreads();
    #pragma unroll
    for (int o = 128; o; o >>= 1) { if (t < o) red[t] += red[t + o]; __syncthreads(); }
    float inv = 1.f / red[0];
    if (t == 0) { g_m[row] = m; g_inv[row] = inv; }

    float acc[8];
    #pragma unroll
    for (int i = 0; i < 8; i++) acc[i] = 0.f;

    __shared__ int   ls[256];
    __shared__ float lw[256];
    __shared__ int   wcnt[8];
    __shared__ int   woff[9];

    for (int pass = 0; pass < 16; pass++) {
        float w = v[pass] * inv;
        bool keep = (w >= 1e-10f);
        unsigned mk = __ballot_sync(0xffffffffu, keep);
        if ((t & 31) == 0) wcnt[t >> 5] = __popc(mk);
        __syncthreads();
        if (t == 0) {
            int o = 0;
            #pragma unroll
            for (int i = 0; i < 8; i++) { woff[i] = o; o += wcnt[i]; }
            woff[8] = o;
        }
        __syncthreads();
        int cnt = woff[8];
        if (cnt > 0) {
            if (keep) {
                int pos = woff[t >> 5] + __popc(mk & ((1u << (t & 31)) - 1u));
                ls[pos] = pass * 256 + t;
                lw[pos] = w;
            }
            __syncthreads();
            for (int e = 0; e < cnt; e++) {
                int   se = ls[e];
                float we = lw[e];
                const float* erow = encb + (size_t)se * K2 + t;
                #pragma unroll
                for (int i = 0; i < 8; i++) acc[i] = fmaf(we, erow[i * 256], acc[i]);
            }
        }
        __syncthreads();
    }
    float* dst = g_ctx2f + (size_t)row * K2 + t;
    #pragma unroll
    for (int i = 0; i < 8; i++) dst[i * 256] = acc[i];
}

// ---------------------------------------------------------------------------
// K3b v2: weights -> out_w [B,S,L], fully coalesced via smem transpose.
// grid (SS/64, BB); tile 64 s x 64 l.
// ---------------------------------------------------------------------------
__global__ __launch_bounds__(256) void k3b(float* __restrict__ out_w) {
    __shared__ float tsm[64 * 68];
    int b = blockIdx.y, s0 = blockIdx.x * 64;
    int t = threadIdx.x;
    {
        int l = t >> 2, q = t & 3;
        int row = b * 64 + l;
        float m = g_m[row], inv = g_inv[row];
        const float4* p = (const float4*)(g_scores + (size_t)row * SS + s0 + q * 16);
        #pragma unroll
        for (int j = 0; j < 4; j++) {
            float4 x = p[j];
            int sbase = q * 16 + j * 4;
            tsm[(sbase + 0) * 68 + l] = expf(x.x - m) * inv;
            tsm[(sbase + 1) * 68 + l] = expf(x.y - m) * inv;
            tsm[(sbase + 2) * 68 + l] = expf(x.z - m) * inv;
            tsm[(sbase + 3) * 68 + l] = expf(x.w - m) * inv;
        }
    }
    __syncthreads();
    {
        int s = t >> 2, q = t & 3;
        float* dst = out_w + ((size_t)b * SS + s0 + s) * LL + q * 16;
        const float* src = tsm + s * 68 + q * 16;
        #pragma unroll
        for (int j = 0; j < 4; j++)
            *(float4*)(dst + j * 4) = *(const float4*)(src + j * 4);
    }
}

// ---------------------------------------------------------------------------
// K5 v2 (mma, fp16 2-term, kg-split-2): out[m,h] = bias[h] + ctx2[m,:].W[h,:]
// grid (32,8) = 256 CTAs; 8 warps = 2 kg x 4 wm; warp tile 16m x 32n.
// ---------------------------------------------------------------------------
__global__ __launch_bounds__(256, 2) void k5_mma(const float* __restrict__ bias,
                                                 float* __restrict__ out) {
    __shared__ float acc[64 * 36];
    const int tid = threadIdx.x, w = tid >> 5, lane = tid & 31;
    const int grp = lane >> 2, tig = lane & 3;
    const int n0 = blockIdx.x * 32;
    const int m0 = blockIdx.y * 64;
    const int kg = w >> 2, wm = w & 3;
    int mA = m0 + wm * 16 + grp, mB = mA + 8;
    const float* a0p = g_ctx2f + (size_t)mA * K2 + kg * 1024 + tig * 2;
    const float* a1p = g_ctx2f + (size_t)mB * K2 + kg * 1024 + tig * 2;

    float d[4][4];
    #pragma unroll
    for (int i = 0; i < 4; i++) { d[i][0]=d[i][1]=d[i][2]=d[i][3]=0.f; }

    #pragma unroll 2
    for (int k0 = 0; k0 < 1024; k0 += 16) {
        float2 v0 = *(const float2*)(a0p + k0);
        float2 v1 = *(const float2*)(a1p + k0);
        float2 v2 = *(const float2*)(a0p + k0 + 8);
        float2 v3 = *(const float2*)(a1p + k0 + 8);
        uint32_t ah[4], al[4];
        split2h(v0.x, v0.y, ah[0], al[0]);
        split2h(v1.x, v1.y, ah[1], al[1]);
        split2h(v2.x, v2.y, ah[2], al[2]);
        split2h(v3.x, v3.y, ah[3], al[3]);
        uint32_t bh0[4], bh1[4];
        #pragma unroll
        for (int nt = 0; nt < 4; nt++) {
            const __half* wp = g_W16 + (size_t)(n0 + nt * 8 + grp) * K2 + kg * 1024 + k0 + 2 * tig;
            bh0[nt] = *(const uint32_t*)(wp);
            bh1[nt] = *(const uint32_t*)(wp + 8);
        }
        #pragma unroll
        for (int nt = 0; nt < 4; nt++) mma_fp16(d[nt], ah, bh0[nt], bh1[nt]);
        #pragma unroll
        for (int nt = 0; nt < 4; nt++) mma_fp16(d[nt], al, bh0[nt], bh1[nt]);
    }

    __syncthreads();
    if (kg == 1) {
        #pragma unroll
        for (int nt = 0; nt < 4; nt++) {
            int cl = nt * 8 + tig * 2;
            int mr = wm * 16 + grp;
            *(float2*)&acc[mr * 36 + cl]       = make_float2(d[nt][0], d[nt][1]);
            *(float2*)&acc[(mr + 8) * 36 + cl] = make_float2(d[nt][2], d[nt][3]);
        }
    }
    __syncthreads();
    if (kg == 0) {
        #pragma unroll
        for (int nt = 0; nt < 4; nt++) {
            int cl = nt * 8 + tig * 2;
            int mr = wm * 16 + grp;
            int hp = n0 + cl;
            float2 bv = *(const float2*)(bias + hp);
            float2 o0 = *(const float2*)&acc[mr * 36 + cl];
            float2 o1 = *(const float2*)&acc[(mr + 8) * 36 + cl];
            float2 r0 = {d[nt][0] + o0.x + bv.x, d[nt][1] + o0.y + bv.y};
            float2 r1 = {d[nt][2] + o1.x + bv.x, d[nt][3] + o1.y + bv.y};
            *(float2*)(out + (size_t)mA * HD + hp) = r0;
            *(float2*)(out + (size_t)mB * HD + hp) = r1;
        }
    }
}

// ---------------------------------------------------------------------------
extern "C" void kernel_launch(void* const* d_in, const int* in_sizes, int n_in,
                              void* d_out, int out_size) {
    (void)in_sizes; (void)n_in; (void)out_size;
    const float* hidden = (const float*)d_in[0];
    const float* enc    = (const float*)d_in[1];
    const float* W      = (const float*)d_in[2];
    const float* bias   = (const float*)d_in[3];
    float* out_ctx = (float*)d_out;
    float* out_w   = (float*)d_out + (size_t)BB * LL * HD;

    const int SM1 = 32768;
    const int SM2 = 34816;
    cudaFuncSetAttribute(k2_mma, cudaFuncAttributeMaxDynamicSharedMemorySize, SM2);

    k0_wt<<<dim3(64, 32), 256>>>(W);
    k_bh<<<64, 256>>>(hidden, bias);
    k1_mma<<<dim3(32, 8), 256, SM1>>>(hidden);
    k2_mma<<<dim3(32, 8), 256, SM2>>>(enc);
    k4_sparse<<<512, 256>>>(enc);
    k3b<<<dim3(64, 8), 256>>>(out_w);
    k5_mma<<<dim3(32, 8), 256>>>(bias, out_ctx);
}